// round 1
// baseline (speedup 1.0000x reference)
#include <cuda_runtime.h>
#include <math.h>

// ---------------- problem constants ----------------
#define HID   3072
#define HEADS 24
#define HD    128
#define MLP_  12288
#define L_    2304
#define TXT_  256
#define IMG   2048                // L - TXT
#define N1    (3*HID + MLP_)      // 21504  (gemm1 N)
#define K2    (HID + MLP_)        // 15360  (gemm2 K)

// ---------------- scratch (static device globals; no allocs) ----------------
__device__ __align__(256) float g_silu[HID];
__device__ __align__(256) float g_emb[3*HID];               // [shift | scale | gate]
__device__ __align__(256) float g_normx[(size_t)L_*HID];    // 28 MB
__device__ __align__(256) float g_proj[(size_t)L_*N1];      // 198 MB
__device__ __align__(256) float g_q[(size_t)HEADS*L_*HD];   // 28 MB
__device__ __align__(256) float g_k[(size_t)HEADS*L_*HD];
__device__ __align__(256) float g_v[(size_t)HEADS*L_*HD];
__device__ __align__(256) float g_cat[(size_t)L_*K2];       // 142 MB [attn | gelu(mlp)]

// ---------------- 1: silu(temb) ----------------
__global__ void silu_kernel(const float* __restrict__ temb) {
    int i = blockIdx.x * 256 + threadIdx.x;
    if (i < HID) {
        float t = temb[i];
        g_silu[i] = t / (1.f + __expf(-t));
    }
}

// ---------------- 2: emb = silu(temb) @ ada_w + ada_b ----------------
__global__ void ada_kernel(const float* __restrict__ ada_w,
                           const float* __restrict__ ada_b) {
    int j = blockIdx.x * 256 + threadIdx.x;   // 0..9215
    if (j >= 3*HID) return;
    float acc = 0.f;
    #pragma unroll 4
    for (int i = 0; i < HID; i++)
        acc += g_silu[i] * ada_w[(size_t)i * (3*HID) + j];
    g_emb[j] = acc + ada_b[j];
}

// ---------------- 3: layernorm + (1+scale)+shift ----------------
__global__ void ln_kernel(const float* __restrict__ x) {
    int t = blockIdx.x;
    const float* row = x + (size_t)t * HID;
    float s = 0.f, s2 = 0.f;
    for (int i = threadIdx.x; i < HID; i += 256) {
        float v = row[i];
        s += v; s2 += v * v;
    }
    #pragma unroll
    for (int o = 16; o; o >>= 1) {
        s  += __shfl_xor_sync(~0u, s,  o);
        s2 += __shfl_xor_sync(~0u, s2, o);
    }
    __shared__ float rs[8], rs2[8], smu, srinv;
    int w = threadIdx.x >> 5, lane = threadIdx.x & 31;
    if (lane == 0) { rs[w] = s; rs2[w] = s2; }
    __syncthreads();
    if (threadIdx.x == 0) {
        float a = 0.f, b = 0.f;
        #pragma unroll
        for (int i = 0; i < 8; i++) { a += rs[i]; b += rs2[i]; }
        float mu = a / HID;
        float var = b / HID - mu * mu;
        smu = mu; srinv = rsqrtf(var + 1e-6f);
    }
    __syncthreads();
    float mu = smu, rinv = srinv;
    for (int i = threadIdx.x; i < HID; i += 256) {
        float sc = 1.f + g_emb[HID + i];
        float sh = g_emb[i];
        g_normx[(size_t)t * HID + i] = (row[i] - mu) * rinv * sc + sh;
    }
}

// ---------------- tiled fp32 GEMM, C[M,N] = A[M,K] @ B[K,N] ----------------
// MODE 0: C = acc + bias[n]
// MODE 1: C = resid + (acc + bias[n]) * gate[n]
template<int MODE>
__global__ __launch_bounds__(256) void sgemm_k(
    const float* __restrict__ A, const float* __restrict__ B,
    const float* __restrict__ bias, const float* __restrict__ resid,
    const float* __restrict__ gate,
    float* __restrict__ C, int M, int N, int K)
{
    __shared__ float As[8][128];
    __shared__ float Bs[8][128];
    int bm = blockIdx.y, bn = blockIdx.x;
    int tid = threadIdx.x;
    int trow = tid / 16, tcol = tid % 16;

    const float* Ab = A + (size_t)bm * 128 * K;
    const float* Bb = B + (size_t)bn * 128;

    int la_m = tid >> 1, la_k = (tid & 1) * 4;
    int lb_k = tid >> 5, lb_n = (tid & 31) * 4;

    float acc[8][8];
    #pragma unroll
    for (int i = 0; i < 8; i++)
        #pragma unroll
        for (int j = 0; j < 8; j++) acc[i][j] = 0.f;

    float4 a4 = *(const float4*)(Ab + (size_t)la_m * K + la_k);
    float4 b4 = *(const float4*)(Bb + (size_t)lb_k * N + lb_n);

    for (int k0 = 0; k0 < K; k0 += 8) {
        As[la_k + 0][la_m] = a4.x;
        As[la_k + 1][la_m] = a4.y;
        As[la_k + 2][la_m] = a4.z;
        As[la_k + 3][la_m] = a4.w;
        *(float4*)&Bs[lb_k][lb_n] = b4;
        __syncthreads();

        if (k0 + 8 < K) {
            a4 = *(const float4*)(Ab + (size_t)la_m * K + (k0 + 8) + la_k);
            b4 = *(const float4*)(Bb + (size_t)(k0 + 8 + lb_k) * N + lb_n);
        }

        #pragma unroll
        for (int kk = 0; kk < 8; kk++) {
            float a[8], b[8];
            *(float4*)(a)     = *(const float4*)&As[kk][trow * 8];
            *(float4*)(a + 4) = *(const float4*)&As[kk][trow * 8 + 4];
            *(float4*)(b)     = *(const float4*)&Bs[kk][tcol * 8];
            *(float4*)(b + 4) = *(const float4*)&Bs[kk][tcol * 8 + 4];
            #pragma unroll
            for (int i = 0; i < 8; i++)
                #pragma unroll
                for (int j = 0; j < 8; j++)
                    acc[i][j] += a[i] * b[j];
        }
        __syncthreads();
    }

    int m0 = bm * 128 + trow * 8;
    int n0 = bn * 128 + tcol * 8;
    #pragma unroll
    for (int i = 0; i < 8; i++) {
        size_t rowoff = (size_t)(m0 + i) * N + n0;
        #pragma unroll
        for (int j4 = 0; j4 < 8; j4 += 4) {
            float4 v;
            float t0 = acc[i][j4 + 0] + bias[n0 + j4 + 0];
            float t1 = acc[i][j4 + 1] + bias[n0 + j4 + 1];
            float t2 = acc[i][j4 + 2] + bias[n0 + j4 + 2];
            float t3 = acc[i][j4 + 3] + bias[n0 + j4 + 3];
            if (MODE == 0) {
                v.x = t0; v.y = t1; v.z = t2; v.w = t3;
            } else {
                v.x = resid[rowoff + j4 + 0] + t0 * gate[n0 + j4 + 0];
                v.y = resid[rowoff + j4 + 1] + t1 * gate[n0 + j4 + 1];
                v.z = resid[rowoff + j4 + 2] + t2 * gate[n0 + j4 + 2];
                v.w = resid[rowoff + j4 + 3] + t3 * gate[n0 + j4 + 3];
            }
            *(float4*)(C + rowoff + j4) = v;
        }
    }
}

// ---------------- 5: qkv split + rmsnorm + rope ----------------
__global__ void qkv_kernel(const float* __restrict__ cosb, const float* __restrict__ sinb,
                           const float* __restrict__ qn,   const float* __restrict__ kn) {
    int t = blockIdx.x, h = blockIdx.y, d = threadIdx.x;  // d: 0..127
    const float* p = g_proj + (size_t)t * N1 + h * HD + d;
    float qv = p[0], kv = p[HID], vv = p[2*HID];

    float sq = qv * qv, sk = kv * kv;
    #pragma unroll
    for (int o = 16; o; o >>= 1) {
        sq += __shfl_xor_sync(~0u, sq, o);
        sk += __shfl_xor_sync(~0u, sk, o);
    }
    __shared__ float rq[4], rk[4];
    int w = d >> 5;
    if ((d & 31) == 0) { rq[w] = sq; rk[w] = sk; }
    __syncthreads();
    sq = rq[0] + rq[1] + rq[2] + rq[3];
    sk = rk[0] + rk[1] + rk[2] + rk[3];
    qv = qv * rsqrtf(sq / HD + 1e-6f) * qn[d];
    kv = kv * rsqrtf(sk / HD + 1e-6f) * kn[d];

    if (t < IMG) {
        float c = cosb[(size_t)t * HD + d];
        float s = sinb[(size_t)t * HD + d];
        float qo = __shfl_xor_sync(~0u, qv, 1);
        float ko = __shfl_xor_sync(~0u, kv, 1);
        float qr = (d & 1) ? qo : -qo;   // rot[2i]=-x[2i+1], rot[2i+1]=x[2i]
        float kr = (d & 1) ? ko : -ko;
        qv = qv * c + qr * s;
        kv = kv * c + kr * s;
    }
    size_t o = ((size_t)h * L_ + t) * HD + d;
    g_q[o] = qv; g_k[o] = kv; g_v[o] = vv;
}

// ---------------- 6: gelu(mlp) into concat buffer ----------------
__global__ void gelu_kernel() {
    size_t idx = (size_t)blockIdx.x * 256 + threadIdx.x;
    if (idx >= (size_t)L_ * MLP_) return;
    int t = (int)(idx / MLP_), c = (int)(idx % MLP_);
    float x = g_proj[(size_t)t * N1 + 3*HID + c];
    float x3 = x * x * x;
    float g = 0.5f * x * (1.f + tanhf(0.7978845608028654f * (x + 0.044715f * x3)));
    g_cat[(size_t)t * K2 + HID + c] = g;
}

// ---------------- 7: flash-style attention ----------------
#define BQ   64
#define BKC  64
#define SSTR 129   // padded row stride (odd -> conflict-free column access)
#define ATTN_SMEM ((3*64*SSTR + 64*65 + 3*64) * sizeof(float))

__global__ __launch_bounds__(256) void attn_kernel() {
    extern __shared__ float sm[];
    float* qs   = sm;                    // [64][129]
    float* ks   = qs + BQ * SSTR;        // [64][129]
    float* vs   = ks + BKC * SSTR;       // [64][129]
    float* st   = vs + BKC * SSTR;       // [64][65]
    float* mrow = st + BQ * 65;          // [64]
    float* lrow = mrow + 64;             // [64]
    float* arow = lrow + 64;             // [64]

    int h  = blockIdx.y;
    int q0 = blockIdx.x * BQ;
    const float* Q = g_q + ((size_t)h * L_ + q0) * HD;
    const float* K = g_k + (size_t)h * L_ * HD;
    const float* V = g_v + (size_t)h * L_ * HD;
    int tid = threadIdx.x;
    int ty = tid >> 5, tx = tid & 31;
    const float scale = 0.08838834764831845f;  // 1/sqrt(128)

    // load q tile (pre-scaled)
    for (int i = tid; i < BQ * HD / 4; i += 256) {
        int r = i / 32, c4 = (i % 32) * 4;
        float4 v4 = *(const float4*)(Q + (size_t)r * HD + c4);
        float* dst = qs + r * SSTR + c4;
        dst[0] = v4.x * scale; dst[1] = v4.y * scale;
        dst[2] = v4.z * scale; dst[3] = v4.w * scale;
    }
    if (tid < 64) { mrow[tid] = -1e30f; lrow[tid] = 0.f; }

    float o[8][4];
    #pragma unroll
    for (int i = 0; i < 8; i++)
        #pragma unroll
        for (int j = 0; j < 4; j++) o[i][j] = 0.f;
    __syncthreads();

    for (int k0 = 0; k0 < L_; k0 += BKC) {
        // load k/v chunk
        for (int i = tid; i < BKC * HD / 4; i += 256) {
            int r = i / 32, c4 = (i % 32) * 4;
            float4 k4 = *(const float4*)(K + (size_t)(k0 + r) * HD + c4);
            float4 v4 = *(const float4*)(V + (size_t)(k0 + r) * HD + c4);
            float* kd = ks + r * SSTR + c4;
            float* vd = vs + r * SSTR + c4;
            kd[0] = k4.x; kd[1] = k4.y; kd[2] = k4.z; kd[3] = k4.w;
            vd[0] = v4.x; vd[1] = v4.y; vd[2] = v4.z; vd[3] = v4.w;
        }
        __syncthreads();

        // scores: rows ty*8+i, key cols tx and tx+32
        float sc[8][2];
        #pragma unroll
        for (int i = 0; i < 8; i++) { sc[i][0] = 0.f; sc[i][1] = 0.f; }
        const float* k0p = ks + tx * SSTR;
        const float* k1p = ks + (tx + 32) * SSTR;
        #pragma unroll 4
        for (int kk = 0; kk < HD; kk++) {
            float kv0 = k0p[kk], kv1 = k1p[kk];
            #pragma unroll
            for (int i = 0; i < 8; i++) {
                float qv = qs[(ty * 8 + i) * SSTR + kk];
                sc[i][0] += qv * kv0;
                sc[i][1] += qv * kv1;
            }
        }
        #pragma unroll
        for (int i = 0; i < 8; i++) {
            st[(ty * 8 + i) * 65 + tx]      = sc[i][0];
            st[(ty * 8 + i) * 65 + tx + 32] = sc[i][1];
        }
        __syncthreads();

        // online softmax: one thread per row
        if (tid < 64) {
            int r = tid;
            float mo = mrow[r];
            float mx = mo;
            #pragma unroll 4
            for (int c = 0; c < BKC; c++) mx = fmaxf(mx, st[r * 65 + c]);
            float alpha = __expf(mo - mx);
            float ssum = 0.f;
            #pragma unroll 4
            for (int c = 0; c < BKC; c++) {
                float e = __expf(st[r * 65 + c] - mx);
                st[r * 65 + c] = e;
                ssum += e;
            }
            lrow[r] = lrow[r] * alpha + ssum;
            mrow[r] = mx;
            arow[r] = alpha;
        }
        __syncthreads();

        // o = o*alpha + P @ V
        #pragma unroll
        for (int i = 0; i < 8; i++) {
            int r = ty * 8 + i;
            float al = arow[r];
            float a0 = o[i][0] * al, a1 = o[i][1] * al;
            float a2 = o[i][2] * al, a3 = o[i][3] * al;
            const float* pr = st + r * 65;
            #pragma unroll 4
            for (int kk = 0; kk < BKC; kk++) {
                float p = pr[kk];
                const float* vr = vs + kk * SSTR;
                a0 += p * vr[tx];
                a1 += p * vr[tx + 32];
                a2 += p * vr[tx + 64];
                a3 += p * vr[tx + 96];
            }
            o[i][0] = a0; o[i][1] = a1; o[i][2] = a2; o[i][3] = a3;
        }
        __syncthreads();
    }

    #pragma unroll
    for (int i = 0; i < 8; i++) {
        int r = ty * 8 + i;
        float inv = 1.f / lrow[r];
        float* dst = g_cat + (size_t)(q0 + r) * K2 + h * HD;
        dst[tx]      = o[i][0] * inv;
        dst[tx + 32] = o[i][1] * inv;
        dst[tx + 64] = o[i][2] * inv;
        dst[tx + 96] = o[i][3] * inv;
    }
}

// ---------------- launch ----------------
extern "C" void kernel_launch(void* const* d_in, const int* in_sizes, int n_in,
                              void* d_out, int out_size) {
    const float* hidden = (const float*)d_in[0];
    const float* temb   = (const float*)d_in[1];
    const float* cosb   = (const float*)d_in[2];
    const float* sinb   = (const float*)d_in[3];
    const float* ada_w  = (const float*)d_in[4];
    const float* ada_b  = (const float*)d_in[5];
    const float* lin1_w = (const float*)d_in[6];
    const float* lin1_b = (const float*)d_in[7];
    const float* lin2_w = (const float*)d_in[8];
    const float* lin2_b = (const float*)d_in[9];
    const float* qn_w   = (const float*)d_in[10];
    const float* kn_w   = (const float*)d_in[11];
    float* out = (float*)d_out;

    float *p_normx, *p_proj, *p_cat, *p_emb;
    cudaGetSymbolAddress((void**)&p_normx, g_normx);
    cudaGetSymbolAddress((void**)&p_proj,  g_proj);
    cudaGetSymbolAddress((void**)&p_cat,   g_cat);
    cudaGetSymbolAddress((void**)&p_emb,   g_emb);

    cudaFuncSetAttribute(attn_kernel,
                         cudaFuncAttributeMaxDynamicSharedMemorySize,
                         (int)ATTN_SMEM);

    silu_kernel<<<(HID + 255) / 256, 256>>>(temb);
    ada_kernel<<<(3 * HID + 255) / 256, 256>>>(ada_w, ada_b);
    ln_kernel<<<L_, 256>>>(hidden);

    // GEMM1: normx(2304x3072) @ lin1_w(3072x21504) -> proj
    sgemm_k<0><<<dim3(N1 / 128, L_ / 128), 256>>>(
        p_normx, lin1_w, lin1_b, nullptr, nullptr, p_proj, L_, N1, HID);

    qkv_kernel<<<dim3(L_, HEADS), HD>>>(cosb, sinb, qn_w, kn_w);
    gelu_kernel<<<(int)(((size_t)L_ * MLP_ + 255) / 256), 256>>>();
    attn_kernel<<<dim3(L_ / BQ, HEADS), 256, ATTN_SMEM>>>();

    // GEMM2: cat(2304x15360) @ lin2_w(15360x3072) -> out (fused bias+gate+residual)
    sgemm_k<1><<<dim3(HID / 128, L_ / 128), 256>>>(
        p_cat, lin2_w, lin2_b, hidden, p_emb + 2 * HID, out, L_, HID, K2);
}

// round 2
// speedup vs baseline: 1.8406x; 1.8406x over previous
#include <cuda_runtime.h>
#include <math.h>
#include <stdint.h>

// ---------------- problem constants ----------------
#define HID   3072
#define HEADS 24
#define HD    128
#define MLP_  12288
#define L_    2304
#define TXT_  256
#define IMG   2048                // L - TXT
#define N1    (3*HID + MLP_)      // 21504  (gemm1 N)
#define K2    (HID + MLP_)        // 15360  (gemm2 K)

// ---------------- scratch (static device globals; no allocs) ----------------
__device__ __align__(256) float g_silu[HID];
__device__ __align__(256) float g_emb[3*HID];               // [shift | scale | gate]
__device__ __align__(256) float g_normx[(size_t)L_*HID];
__device__ __align__(256) float g_proj[(size_t)L_*N1];
__device__ __align__(256) float g_q[(size_t)HEADS*L_*HD];
__device__ __align__(256) float g_k[(size_t)HEADS*L_*HD];
__device__ __align__(256) float g_v[(size_t)HEADS*L_*HD];
__device__ __align__(256) float g_cat[(size_t)L_*K2];       // [attn | gelu(mlp)]

// ---------------- 1: silu(temb) ----------------
__global__ void silu_kernel(const float* __restrict__ temb) {
    int i = blockIdx.x * 256 + threadIdx.x;
    if (i < HID) {
        float t = temb[i];
        g_silu[i] = t / (1.f + __expf(-t));
    }
}

// ---------------- 2: emb = silu(temb) @ ada_w + ada_b ----------------
__global__ void ada_kernel(const float* __restrict__ ada_w,
                           const float* __restrict__ ada_b) {
    int j = blockIdx.x * 256 + threadIdx.x;
    if (j >= 3*HID) return;
    float acc = 0.f;
    #pragma unroll 4
    for (int i = 0; i < HID; i++)
        acc += g_silu[i] * ada_w[(size_t)i * (3*HID) + j];
    g_emb[j] = acc + ada_b[j];
}

// ---------------- 3: layernorm + (1+scale)+shift ----------------
__global__ void ln_kernel(const float* __restrict__ x) {
    int t = blockIdx.x;
    const float* row = x + (size_t)t * HID;
    float s = 0.f, s2 = 0.f;
    for (int i = threadIdx.x; i < HID; i += 256) {
        float v = row[i];
        s += v; s2 += v * v;
    }
    #pragma unroll
    for (int o = 16; o; o >>= 1) {
        s  += __shfl_xor_sync(~0u, s,  o);
        s2 += __shfl_xor_sync(~0u, s2, o);
    }
    __shared__ float rs[8], rs2[8], smu, srinv;
    int w = threadIdx.x >> 5, lane = threadIdx.x & 31;
    if (lane == 0) { rs[w] = s; rs2[w] = s2; }
    __syncthreads();
    if (threadIdx.x == 0) {
        float a = 0.f, b = 0.f;
        #pragma unroll
        for (int i = 0; i < 8; i++) { a += rs[i]; b += rs2[i]; }
        float mu = a / HID;
        float var = b / HID - mu * mu;
        smu = mu; srinv = rsqrtf(var + 1e-6f);
    }
    __syncthreads();
    float mu = smu, rinv = srinv;
    for (int i = threadIdx.x; i < HID; i += 256) {
        float sc = 1.f + g_emb[HID + i];
        float sh = g_emb[i];
        g_normx[(size_t)t * HID + i] = (row[i] - mu) * rinv * sc + sh;
    }
}

// ---------------- tf32 helpers ----------------
__device__ __forceinline__ float f2tf(float x) {
    uint32_t u;
    asm("cvt.rna.tf32.f32 %0, %1;" : "=r"(u) : "f"(x));
    return __uint_as_float(u);
}

__device__ __forceinline__ void mma_tf32(float& c0, float& c1, float& c2, float& c3,
                                         uint32_t a0, uint32_t a1, uint32_t a2, uint32_t a3,
                                         uint32_t b0, uint32_t b1) {
    asm volatile("mma.sync.aligned.m16n8k8.row.col.f32.tf32.tf32.f32 "
                 "{%0,%1,%2,%3}, {%4,%5,%6,%7}, {%8,%9}, {%0,%1,%2,%3};"
                 : "+f"(c0), "+f"(c1), "+f"(c2), "+f"(c3)
                 : "r"(a0), "r"(a1), "r"(a2), "r"(a3), "r"(b0), "r"(b1));
}

// ---------------- tf32 tensor-core GEMM, C[M,N] = A[M,K] @ B[K,N] ----------------
// Tiles: 128x128x16. 8 warps (2x4), each warp 64x32 via m16n8k8 (4x4 mma tiles).
// Smem stride 136 (136%32==8) -> fragment LDS pattern 8*k+m hits all banks.
// MODE 0: C = acc + bias[n]
// MODE 1: C = resid + (acc + bias[n]) * gate[n]
#define GSTR 136
template<int MODE>
__global__ __launch_bounds__(256) void tgemm_k(
    const float* __restrict__ A, const float* __restrict__ B,
    const float* __restrict__ bias, const float* __restrict__ resid,
    const float* __restrict__ gate,
    float* __restrict__ C, int M, int N, int K)
{
    __shared__ float As[2][16][GSTR];
    __shared__ float Bs[2][16][GSTR];

    int tid  = threadIdx.x;
    int wid  = tid >> 5, lane = tid & 31;
    int wm   = wid >> 2, wn = wid & 3;          // warp grid 2x4
    int bm = blockIdx.y, bn = blockIdx.x;

    const float* Ab = A + (size_t)bm * 128 * K;
    const float* Bb = B + (size_t)bn * 128;

    // A loads: 128 rows x 16 k = 2048 -> 8 per thread (2 float4)
    int la_m = tid >> 1, la_k = (tid & 1) * 8;
    // B loads: 16 rows x 128 n -> lb_k row, cols lb_n and lb_n+64
    int lb_k = tid >> 4, lb_n = (tid & 15) * 4;

    float acc[4][4][4];
    #pragma unroll
    for (int i = 0; i < 4; i++)
        #pragma unroll
        for (int j = 0; j < 4; j++)
            #pragma unroll
            for (int q = 0; q < 4; q++) acc[i][j][q] = 0.f;

    int nkt = K / 16;

    // prefetch tile 0
    float4 pa0 = *(const float4*)(Ab + (size_t)la_m * K + la_k);
    float4 pa1 = *(const float4*)(Ab + (size_t)la_m * K + la_k + 4);
    float4 pb0 = *(const float4*)(Bb + (size_t)lb_k * N + lb_n);
    float4 pb1 = *(const float4*)(Bb + (size_t)lb_k * N + lb_n + 64);

    int buf = 0;
    // store tile 0
    {
        As[0][la_k+0][la_m] = f2tf(pa0.x); As[0][la_k+1][la_m] = f2tf(pa0.y);
        As[0][la_k+2][la_m] = f2tf(pa0.z); As[0][la_k+3][la_m] = f2tf(pa0.w);
        As[0][la_k+4][la_m] = f2tf(pa1.x); As[0][la_k+5][la_m] = f2tf(pa1.y);
        As[0][la_k+6][la_m] = f2tf(pa1.z); As[0][la_k+7][la_m] = f2tf(pa1.w);
        Bs[0][lb_k][lb_n+0] = f2tf(pb0.x); Bs[0][lb_k][lb_n+1] = f2tf(pb0.y);
        Bs[0][lb_k][lb_n+2] = f2tf(pb0.z); Bs[0][lb_k][lb_n+3] = f2tf(pb0.w);
        Bs[0][lb_k][lb_n+64] = f2tf(pb1.x); Bs[0][lb_k][lb_n+65] = f2tf(pb1.y);
        Bs[0][lb_k][lb_n+66] = f2tf(pb1.z); Bs[0][lb_k][lb_n+67] = f2tf(pb1.w);
    }
    __syncthreads();

    for (int kt = 0; kt < nkt; kt++) {
        // prefetch next tile
        if (kt + 1 < nkt) {
            int kg = (kt + 1) * 16;
            pa0 = *(const float4*)(Ab + (size_t)la_m * K + kg + la_k);
            pa1 = *(const float4*)(Ab + (size_t)la_m * K + kg + la_k + 4);
            pb0 = *(const float4*)(Bb + (size_t)(kg + lb_k) * N + lb_n);
            pb1 = *(const float4*)(Bb + (size_t)(kg + lb_k) * N + lb_n + 64);
        }

        // compute: two k8 steps
        #pragma unroll
        for (int ks = 0; ks < 2; ks++) {
            int kr = ks * 8 + (lane & 3);
            uint32_t af[4][4], bf[4][2];
            #pragma unroll
            for (int mt = 0; mt < 4; mt++) {
                int m0 = wm * 64 + mt * 16 + (lane >> 2);
                af[mt][0] = __float_as_uint(As[buf][kr  ][m0]);
                af[mt][1] = __float_as_uint(As[buf][kr  ][m0 + 8]);
                af[mt][2] = __float_as_uint(As[buf][kr+4][m0]);
                af[mt][3] = __float_as_uint(As[buf][kr+4][m0 + 8]);
            }
            #pragma unroll
            for (int nt = 0; nt < 4; nt++) {
                int n0 = wn * 32 + nt * 8 + (lane >> 2);
                bf[nt][0] = __float_as_uint(Bs[buf][kr  ][n0]);
                bf[nt][1] = __float_as_uint(Bs[buf][kr+4][n0]);
            }
            #pragma unroll
            for (int mt = 0; mt < 4; mt++)
                #pragma unroll
                for (int nt = 0; nt < 4; nt++)
                    mma_tf32(acc[mt][nt][0], acc[mt][nt][1], acc[mt][nt][2], acc[mt][nt][3],
                             af[mt][0], af[mt][1], af[mt][2], af[mt][3],
                             bf[nt][0], bf[nt][1]);
        }

        // store next tile
        if (kt + 1 < nkt) {
            int nb = buf ^ 1;
            __syncthreads();
            As[nb][la_k+0][la_m] = f2tf(pa0.x); As[nb][la_k+1][la_m] = f2tf(pa0.y);
            As[nb][la_k+2][la_m] = f2tf(pa0.z); As[nb][la_k+3][la_m] = f2tf(pa0.w);
            As[nb][la_k+4][la_m] = f2tf(pa1.x); As[nb][la_k+5][la_m] = f2tf(pa1.y);
            As[nb][la_k+6][la_m] = f2tf(pa1.z); As[nb][la_k+7][la_m] = f2tf(pa1.w);
            Bs[nb][lb_k][lb_n+0] = f2tf(pb0.x); Bs[nb][lb_k][lb_n+1] = f2tf(pb0.y);
            Bs[nb][lb_k][lb_n+2] = f2tf(pb0.z); Bs[nb][lb_k][lb_n+3] = f2tf(pb0.w);
            Bs[nb][lb_k][lb_n+64] = f2tf(pb1.x); Bs[nb][lb_k][lb_n+65] = f2tf(pb1.y);
            Bs[nb][lb_k][lb_n+66] = f2tf(pb1.z); Bs[nb][lb_k][lb_n+67] = f2tf(pb1.w);
            __syncthreads();
            buf = nb;
        }
    }

    // epilogue
    #pragma unroll
    for (int mt = 0; mt < 4; mt++) {
        int r0 = bm * 128 + wm * 64 + mt * 16 + (lane >> 2);
        #pragma unroll
        for (int nt = 0; nt < 4; nt++) {
            int c0 = bn * 128 + wn * 32 + nt * 8 + 2 * (lane & 3);
            float bia0 = bias[c0], bia1 = bias[c0 + 1];
            size_t o0 = (size_t)r0 * N + c0;
            size_t o1 = (size_t)(r0 + 8) * N + c0;
            float t00 = acc[mt][nt][0] + bia0, t01 = acc[mt][nt][1] + bia1;
            float t10 = acc[mt][nt][2] + bia0, t11 = acc[mt][nt][3] + bia1;
            if (MODE == 0) {
                *(float2*)(C + o0) = make_float2(t00, t01);
                *(float2*)(C + o1) = make_float2(t10, t11);
            } else {
                float gg0 = gate[c0], gg1 = gate[c0 + 1];
                float2 r_0 = *(const float2*)(resid + o0);
                float2 r_1 = *(const float2*)(resid + o1);
                *(float2*)(C + o0) = make_float2(r_0.x + t00 * gg0, r_0.y + t01 * gg1);
                *(float2*)(C + o1) = make_float2(r_1.x + t10 * gg0, r_1.y + t11 * gg1);
            }
        }
    }
}

// ---------------- 5: qkv split + rmsnorm + rope ----------------
__global__ void qkv_kernel(const float* __restrict__ cosb, const float* __restrict__ sinb,
                           const float* __restrict__ qn,   const float* __restrict__ kn) {
    int t = blockIdx.x, h = blockIdx.y, d = threadIdx.x;
    const float* p = g_proj + (size_t)t * N1 + h * HD + d;
    float qv = p[0], kv = p[HID], vv = p[2*HID];

    float sq = qv * qv, sk = kv * kv;
    #pragma unroll
    for (int o = 16; o; o >>= 1) {
        sq += __shfl_xor_sync(~0u, sq, o);
        sk += __shfl_xor_sync(~0u, sk, o);
    }
    __shared__ float rq[4], rk[4];
    int w = d >> 5;
    if ((d & 31) == 0) { rq[w] = sq; rk[w] = sk; }
    __syncthreads();
    sq = rq[0] + rq[1] + rq[2] + rq[3];
    sk = rk[0] + rk[1] + rk[2] + rk[3];
    qv = qv * rsqrtf(sq / HD + 1e-6f) * qn[d];
    kv = kv * rsqrtf(sk / HD + 1e-6f) * kn[d];

    if (t < IMG) {
        float c = cosb[(size_t)t * HD + d];
        float s = sinb[(size_t)t * HD + d];
        float qo = __shfl_xor_sync(~0u, qv, 1);
        float ko = __shfl_xor_sync(~0u, kv, 1);
        float qr = (d & 1) ? qo : -qo;
        float kr = (d & 1) ? ko : -ko;
        qv = qv * c + qr * s;
        kv = kv * c + kr * s;
    }
    size_t o = ((size_t)h * L_ + t) * HD + d;
    g_q[o] = qv; g_k[o] = kv; g_v[o] = vv;
}

// ---------------- 6: gelu(mlp) into concat buffer ----------------
__global__ void gelu_kernel() {
    size_t idx = (size_t)blockIdx.x * 256 + threadIdx.x;
    if (idx >= (size_t)L_ * MLP_) return;
    int t = (int)(idx / MLP_), c = (int)(idx % MLP_);
    float x = g_proj[(size_t)t * N1 + 3*HID + c];
    float x3 = x * x * x;
    float g = 0.5f * x * (1.f + tanhf(0.7978845608028654f * (x + 0.044715f * x3)));
    g_cat[(size_t)t * K2 + HID + c] = g;
}

// ---------------- 7: flash-style attention (fp32) ----------------
#define BQ   64
#define BKC  64
#define SSTR 129
#define ATTN_SMEM ((3*64*SSTR + 64*65 + 3*64) * sizeof(float))

__global__ __launch_bounds__(256) void attn_kernel() {
    extern __shared__ float sm[];
    float* qs   = sm;
    float* ks   = qs + BQ * SSTR;
    float* vs   = ks + BKC * SSTR;
    float* st   = vs + BKC * SSTR;
    float* mrow = st + BQ * 65;
    float* lrow = mrow + 64;
    float* arow = lrow + 64;

    int h  = blockIdx.y;
    int q0 = blockIdx.x * BQ;
    const float* Q = g_q + ((size_t)h * L_ + q0) * HD;
    const float* K = g_k + (size_t)h * L_ * HD;
    const float* V = g_v + (size_t)h * L_ * HD;
    int tid = threadIdx.x;
    int ty = tid >> 5, tx = tid & 31;
    const float scale = 0.08838834764831845f;

    for (int i = tid; i < BQ * HD / 4; i += 256) {
        int r = i / 32, c4 = (i % 32) * 4;
        float4 v4 = *(const float4*)(Q + (size_t)r * HD + c4);
        float* dst = qs + r * SSTR + c4;
        dst[0] = v4.x * scale; dst[1] = v4.y * scale;
        dst[2] = v4.z * scale; dst[3] = v4.w * scale;
    }
    if (tid < 64) { mrow[tid] = -1e30f; lrow[tid] = 0.f; }

    float o[8][4];
    #pragma unroll
    for (int i = 0; i < 8; i++)
        #pragma unroll
        for (int j = 0; j < 4; j++) o[i][j] = 0.f;
    __syncthreads();

    for (int k0 = 0; k0 < L_; k0 += BKC) {
        for (int i = tid; i < BKC * HD / 4; i += 256) {
            int r = i / 32, c4 = (i % 32) * 4;
            float4 k4 = *(const float4*)(K + (size_t)(k0 + r) * HD + c4);
            float4 v4 = *(const float4*)(V + (size_t)(k0 + r) * HD + c4);
            float* kd = ks + r * SSTR + c4;
            float* vd = vs + r * SSTR + c4;
            kd[0] = k4.x; kd[1] = k4.y; kd[2] = k4.z; kd[3] = k4.w;
            vd[0] = v4.x; vd[1] = v4.y; vd[2] = v4.z; vd[3] = v4.w;
        }
        __syncthreads();

        float sc[8][2];
        #pragma unroll
        for (int i = 0; i < 8; i++) { sc[i][0] = 0.f; sc[i][1] = 0.f; }
        const float* k0p = ks + tx * SSTR;
        const float* k1p = ks + (tx + 32) * SSTR;
        #pragma unroll 4
        for (int kk = 0; kk < HD; kk++) {
            float kv0 = k0p[kk], kv1 = k1p[kk];
            #pragma unroll
            for (int i = 0; i < 8; i++) {
                float qv = qs[(ty * 8 + i) * SSTR + kk];
                sc[i][0] += qv * kv0;
                sc[i][1] += qv * kv1;
            }
        }
        #pragma unroll
        for (int i = 0; i < 8; i++) {
            st[(ty * 8 + i) * 65 + tx]      = sc[i][0];
            st[(ty * 8 + i) * 65 + tx + 32] = sc[i][1];
        }
        __syncthreads();

        if (tid < 64) {
            int r = tid;
            float mo = mrow[r];
            float mx = mo;
            #pragma unroll 4
            for (int c = 0; c < BKC; c++) mx = fmaxf(mx, st[r * 65 + c]);
            float alpha = __expf(mo - mx);
            float ssum = 0.f;
            #pragma unroll 4
            for (int c = 0; c < BKC; c++) {
                float e = __expf(st[r * 65 + c] - mx);
                st[r * 65 + c] = e;
                ssum += e;
            }
            lrow[r] = lrow[r] * alpha + ssum;
            mrow[r] = mx;
            arow[r] = alpha;
        }
        __syncthreads();

        #pragma unroll
        for (int i = 0; i < 8; i++) {
            int r = ty * 8 + i;
            float al = arow[r];
            float a0 = o[i][0] * al, a1 = o[i][1] * al;
            float a2 = o[i][2] * al, a3 = o[i][3] * al;
            const float* pr = st + r * 65;
            #pragma unroll 4
            for (int kk = 0; kk < BKC; kk++) {
                float p = pr[kk];
                const float* vr = vs + kk * SSTR;
                a0 += p * vr[tx];
                a1 += p * vr[tx + 32];
                a2 += p * vr[tx + 64];
                a3 += p * vr[tx + 96];
            }
            o[i][0] = a0; o[i][1] = a1; o[i][2] = a2; o[i][3] = a3;
        }
        __syncthreads();
    }

    #pragma unroll
    for (int i = 0; i < 8; i++) {
        int r = ty * 8 + i;
        float inv = 1.f / lrow[r];
        float* dst = g_cat + (size_t)(q0 + r) * K2 + h * HD;
        dst[tx]      = o[i][0] * inv;
        dst[tx + 32] = o[i][1] * inv;
        dst[tx + 64] = o[i][2] * inv;
        dst[tx + 96] = o[i][3] * inv;
    }
}

// ---------------- launch ----------------
extern "C" void kernel_launch(void* const* d_in, const int* in_sizes, int n_in,
                              void* d_out, int out_size) {
    const float* hidden = (const float*)d_in[0];
    const float* temb   = (const float*)d_in[1];
    const float* cosb   = (const float*)d_in[2];
    const float* sinb   = (const float*)d_in[3];
    const float* ada_w  = (const float*)d_in[4];
    const float* ada_b  = (const float*)d_in[5];
    const float* lin1_w = (const float*)d_in[6];
    const float* lin1_b = (const float*)d_in[7];
    const float* lin2_w = (const float*)d_in[8];
    const float* lin2_b = (const float*)d_in[9];
    const float* qn_w   = (const float*)d_in[10];
    const float* kn_w   = (const float*)d_in[11];
    float* out = (float*)d_out;

    float *p_normx, *p_proj, *p_cat, *p_emb;
    cudaGetSymbolAddress((void**)&p_normx, g_normx);
    cudaGetSymbolAddress((void**)&p_proj,  g_proj);
    cudaGetSymbolAddress((void**)&p_cat,   g_cat);
    cudaGetSymbolAddress((void**)&p_emb,   g_emb);

    cudaFuncSetAttribute(attn_kernel,
                         cudaFuncAttributeMaxDynamicSharedMemorySize,
                         (int)ATTN_SMEM);

    silu_kernel<<<(HID + 255) / 256, 256>>>(temb);
    ada_kernel<<<(3 * HID + 255) / 256, 256>>>(ada_w, ada_b);
    ln_kernel<<<L_, 256>>>(hidden);

    // GEMM1: normx(2304x3072) @ lin1_w(3072x21504) -> proj
    tgemm_k<0><<<dim3(N1 / 128, L_ / 128), 256>>>(
        p_normx, lin1_w, lin1_b, nullptr, nullptr, p_proj, L_, N1, HID);

    qkv_kernel<<<dim3(L_, HEADS), HD>>>(cosb, sinb, qn_w, kn_w);
    gelu_kernel<<<(int)(((size_t)L_ * MLP_ + 255) / 256), 256>>>();
    attn_kernel<<<dim3(L_ / BQ, HEADS), 256, ATTN_SMEM>>>();

    // GEMM2: cat(2304x15360) @ lin2_w(15360x3072) -> out (fused bias+gate+residual)
    tgemm_k<1><<<dim3(HID / 128, L_ / 128), 256>>>(
        p_cat, lin2_w, lin2_b, hidden, p_emb + 2 * HID, out, L_, HID, K2);
}

// round 3
// speedup vs baseline: 2.0451x; 1.1112x over previous
#include <cuda_runtime.h>
#include <math.h>
#include <stdint.h>

// ---------------- problem constants ----------------
#define HID   3072
#define HEADS 24
#define HD    128
#define MLP_  12288
#define L_    2304
#define TXT_  256
#define IMG   2048
#define N1    (3*HID + MLP_)      // 21504
#define K2    (HID + MLP_)        // 15360
#define QKV3  (3*HID)             // 9216

// ---------------- scratch ----------------
__device__ __align__(256) float g_silu[HID];
__device__ __align__(256) float g_emb[3*HID];
__device__ __align__(256) float g_normx[(size_t)L_*HID];
__device__ __align__(256) float g_proj[(size_t)L_*QKV3];    // qkv only
__device__ __align__(256) float g_q[(size_t)HEADS*L_*HD];
__device__ __align__(256) float g_k[(size_t)HEADS*L_*HD];
__device__ __align__(256) float g_v[(size_t)HEADS*L_*HD];
__device__ __align__(256) float g_cat[(size_t)L_*K2];       // [attn | gelu(mlp)]

// ---------------- tf32 helpers ----------------
__device__ __forceinline__ float f2tf(float x) {
    uint32_t u;
    asm("cvt.rna.tf32.f32 %0, %1;" : "=r"(u) : "f"(x));
    return __uint_as_float(u);
}
__device__ __forceinline__ void mma_tf32(float& c0, float& c1, float& c2, float& c3,
                                         uint32_t a0, uint32_t a1, uint32_t a2, uint32_t a3,
                                         uint32_t b0, uint32_t b1) {
    asm volatile("mma.sync.aligned.m16n8k8.row.col.f32.tf32.tf32.f32 "
                 "{%0,%1,%2,%3}, {%4,%5,%6,%7}, {%8,%9}, {%0,%1,%2,%3};"
                 : "+f"(c0), "+f"(c1), "+f"(c2), "+f"(c3)
                 : "r"(a0), "r"(a1), "r"(a2), "r"(a3), "r"(b0), "r"(b1));
}

// ---------------- 1: silu ----------------
__global__ void silu_kernel(const float* __restrict__ temb) {
    int i = blockIdx.x * 256 + threadIdx.x;
    if (i < HID) {
        float t = temb[i];
        g_silu[i] = t / (1.f + __expf(-t));
    }
}

// ---------------- 2: adaLN GEMV ----------------
__global__ void ada_kernel(const float* __restrict__ ada_w,
                           const float* __restrict__ ada_b) {
    int j = blockIdx.x * 256 + threadIdx.x;
    if (j >= 3*HID) return;
    float acc = 0.f;
    #pragma unroll 4
    for (int i = 0; i < HID; i++)
        acc += g_silu[i] * ada_w[(size_t)i * (3*HID) + j];
    g_emb[j] = acc + ada_b[j];
}

// ---------------- 3: layernorm + scale/shift ----------------
__global__ void ln_kernel(const float* __restrict__ x) {
    int t = blockIdx.x;
    const float* row = x + (size_t)t * HID;
    float s = 0.f, s2 = 0.f;
    for (int i = threadIdx.x; i < HID; i += 256) {
        float v = row[i];
        s += v; s2 += v * v;
    }
    #pragma unroll
    for (int o = 16; o; o >>= 1) {
        s  += __shfl_xor_sync(~0u, s,  o);
        s2 += __shfl_xor_sync(~0u, s2, o);
    }
    __shared__ float rs[8], rs2[8], smu, srinv;
    int w = threadIdx.x >> 5, lane = threadIdx.x & 31;
    if (lane == 0) { rs[w] = s; rs2[w] = s2; }
    __syncthreads();
    if (threadIdx.x == 0) {
        float a = 0.f, b = 0.f;
        #pragma unroll
        for (int i = 0; i < 8; i++) { a += rs[i]; b += rs2[i]; }
        float mu = a / HID;
        float var = b / HID - mu * mu;
        smu = mu; srinv = rsqrtf(var + 1e-6f);
    }
    __syncthreads();
    float mu = smu, rinv = srinv;
    for (int i = threadIdx.x; i < HID; i += 256) {
        float sc = 1.f + g_emb[HID + i];
        float sh = g_emb[i];
        g_normx[(size_t)t * HID + i] = (row[i] - mu) * rinv * sc + sh;
    }
}

// ---------------- tf32 GEMM: 128x128x16 tiles, 4 warps of 64x64 ----------------
// MODE 0: C = acc + bias
// MODE 1: C = resid + (acc + bias) * gate
// MODE 2: split epilogue: global n < QKV3 -> C (stride QKV3); else gelu -> C2 (stride K2, +HID offset)
#define GSTR 136
template<int MODE>
__global__ __launch_bounds__(128) void tgemm_k(
    const float* __restrict__ A, const float* __restrict__ B,
    const float* __restrict__ bias, const float* __restrict__ resid,
    const float* __restrict__ gate,
    float* __restrict__ C, float* __restrict__ C2, int M, int N, int K)
{
    __shared__ float As[2][16][GSTR];
    __shared__ float Bs[2][16][GSTR];

    int tid = threadIdx.x;
    int wid = tid >> 5, lane = tid & 31;
    int wm = wid >> 1, wn = wid & 1;             // 2x2 warp grid, 64x64 each
    int bm = blockIdx.y, bn = blockIdx.x;

    const float* Ab = A + (size_t)bm * 128 * K;
    const float* Bb = B + (size_t)bn * 128;

    int la_m = tid;                               // A: row tid, 16 k
    int lb_k = tid >> 3, lb_n = (tid & 7) * 16;   // B: row lb_k, 16 n

    float acc[4][8][4];
    #pragma unroll
    for (int i = 0; i < 4; i++)
        #pragma unroll
        for (int j = 0; j < 8; j++)
            #pragma unroll
            for (int q = 0; q < 4; q++) acc[i][j][q] = 0.f;

    int nkt = K / 16;
    float4 pa[4], pb[4];
    #pragma unroll
    for (int j = 0; j < 4; j++) {
        pa[j] = *(const float4*)(Ab + (size_t)la_m * K + j * 4);
        pb[j] = *(const float4*)(Bb + (size_t)lb_k * N + lb_n + j * 4);
    }

    int buf = 0;
    {
        #pragma unroll
        for (int j = 0; j < 4; j++) {
            As[0][j*4+0][la_m] = f2tf(pa[j].x);
            As[0][j*4+1][la_m] = f2tf(pa[j].y);
            As[0][j*4+2][la_m] = f2tf(pa[j].z);
            As[0][j*4+3][la_m] = f2tf(pa[j].w);
            float4 t = make_float4(f2tf(pb[j].x), f2tf(pb[j].y), f2tf(pb[j].z), f2tf(pb[j].w));
            *(float4*)&Bs[0][lb_k][lb_n + j*4] = t;
        }
    }
    __syncthreads();

    for (int kt = 0; kt < nkt; kt++) {
        if (kt + 1 < nkt) {
            int kg = (kt + 1) * 16;
            #pragma unroll
            for (int j = 0; j < 4; j++) {
                pa[j] = *(const float4*)(Ab + (size_t)la_m * K + kg + j * 4);
                pb[j] = *(const float4*)(Bb + (size_t)(kg + lb_k) * N + lb_n + j * 4);
            }
        }

        #pragma unroll
        for (int ks = 0; ks < 2; ks++) {
            int kr = ks * 8 + (lane & 3);
            uint32_t af[4][4], bf[8][2];
            #pragma unroll
            for (int mt = 0; mt < 4; mt++) {
                int m0 = wm * 64 + mt * 16 + (lane >> 2);
                af[mt][0] = __float_as_uint(As[buf][kr  ][m0]);
                af[mt][1] = __float_as_uint(As[buf][kr  ][m0 + 8]);
                af[mt][2] = __float_as_uint(As[buf][kr+4][m0]);
                af[mt][3] = __float_as_uint(As[buf][kr+4][m0 + 8]);
            }
            #pragma unroll
            for (int nt = 0; nt < 8; nt++) {
                int n0 = wn * 64 + nt * 8 + (lane >> 2);
                bf[nt][0] = __float_as_uint(Bs[buf][kr  ][n0]);
                bf[nt][1] = __float_as_uint(Bs[buf][kr+4][n0]);
            }
            #pragma unroll
            for (int mt = 0; mt < 4; mt++)
                #pragma unroll
                for (int nt = 0; nt < 8; nt++)
                    mma_tf32(acc[mt][nt][0], acc[mt][nt][1], acc[mt][nt][2], acc[mt][nt][3],
                             af[mt][0], af[mt][1], af[mt][2], af[mt][3],
                             bf[nt][0], bf[nt][1]);
        }

        if (kt + 1 < nkt) {
            int nb = buf ^ 1;
            __syncthreads();
            #pragma unroll
            for (int j = 0; j < 4; j++) {
                As[nb][j*4+0][la_m] = f2tf(pa[j].x);
                As[nb][j*4+1][la_m] = f2tf(pa[j].y);
                As[nb][j*4+2][la_m] = f2tf(pa[j].z);
                As[nb][j*4+3][la_m] = f2tf(pa[j].w);
                float4 t = make_float4(f2tf(pb[j].x), f2tf(pb[j].y), f2tf(pb[j].z), f2tf(pb[j].w));
                *(float4*)&Bs[nb][lb_k][lb_n + j*4] = t;
            }
            __syncthreads();
            buf = nb;
        }
    }

    // epilogue
    #pragma unroll
    for (int mt = 0; mt < 4; mt++) {
        int r0 = bm * 128 + wm * 64 + mt * 16 + (lane >> 2);
        #pragma unroll
        for (int nt = 0; nt < 8; nt++) {
            int c0 = bn * 128 + wn * 64 + nt * 8 + 2 * (lane & 3);
            float bia0 = bias[c0], bia1 = bias[c0 + 1];
            float t00 = acc[mt][nt][0] + bia0, t01 = acc[mt][nt][1] + bia1;
            float t10 = acc[mt][nt][2] + bia0, t11 = acc[mt][nt][3] + bia1;
            if (MODE == 0) {
                size_t o0 = (size_t)r0 * N + c0;
                size_t o1 = (size_t)(r0 + 8) * N + c0;
                *(float2*)(C + o0) = make_float2(t00, t01);
                *(float2*)(C + o1) = make_float2(t10, t11);
            } else if (MODE == 1) {
                size_t o0 = (size_t)r0 * N + c0;
                size_t o1 = (size_t)(r0 + 8) * N + c0;
                float gg0 = gate[c0], gg1 = gate[c0 + 1];
                float2 r_0 = *(const float2*)(resid + o0);
                float2 r_1 = *(const float2*)(resid + o1);
                *(float2*)(C + o0) = make_float2(r_0.x + t00 * gg0, r_0.y + t01 * gg1);
                *(float2*)(C + o1) = make_float2(r_1.x + t10 * gg0, r_1.y + t11 * gg1);
            } else {
                if (c0 < QKV3) {   // uniform per block (QKV3 % 128 == 0)
                    size_t o0 = (size_t)r0 * QKV3 + c0;
                    size_t o1 = (size_t)(r0 + 8) * QKV3 + c0;
                    *(float2*)(C + o0) = make_float2(t00, t01);
                    *(float2*)(C + o1) = make_float2(t10, t11);
                } else {
                    int cc = c0 - QKV3;
                    size_t o0 = (size_t)r0 * K2 + HID + cc;
                    size_t o1 = (size_t)(r0 + 8) * K2 + HID + cc;
                    const float kA = 0.7978845608028654f, kB = 0.044715f;
                    float g00 = 0.5f * t00 * (1.f + tanhf(kA * (t00 + kB * t00 * t00 * t00)));
                    float g01 = 0.5f * t01 * (1.f + tanhf(kA * (t01 + kB * t01 * t01 * t01)));
                    float g10 = 0.5f * t10 * (1.f + tanhf(kA * (t10 + kB * t10 * t10 * t10)));
                    float g11 = 0.5f * t11 * (1.f + tanhf(kA * (t11 + kB * t11 * t11 * t11)));
                    *(float2*)(C2 + o0) = make_float2(g00, g01);
                    *(float2*)(C2 + o1) = make_float2(g10, g11);
                }
            }
        }
    }
}

// ---------------- 5: qkv split + rmsnorm + rope ----------------
__global__ void qkv_kernel(const float* __restrict__ cosb, const float* __restrict__ sinb,
                           const float* __restrict__ qn,   const float* __restrict__ kn) {
    int t = blockIdx.x, h = blockIdx.y, d = threadIdx.x;
    const float* p = g_proj + (size_t)t * QKV3 + h * HD + d;
    float qv = p[0], kv = p[HID], vv = p[2*HID];

    float sq = qv * qv, sk = kv * kv;
    #pragma unroll
    for (int o = 16; o; o >>= 1) {
        sq += __shfl_xor_sync(~0u, sq, o);
        sk += __shfl_xor_sync(~0u, sk, o);
    }
    __shared__ float rq[4], rk[4];
    int w = d >> 5;
    if ((d & 31) == 0) { rq[w] = sq; rk[w] = sk; }
    __syncthreads();
    sq = rq[0] + rq[1] + rq[2] + rq[3];
    sk = rk[0] + rk[1] + rk[2] + rk[3];
    qv = qv * rsqrtf(sq / HD + 1e-6f) * qn[d];
    kv = kv * rsqrtf(sk / HD + 1e-6f) * kn[d];

    if (t < IMG) {
        float c = cosb[(size_t)t * HD + d];
        float s = sinb[(size_t)t * HD + d];
        float qo = __shfl_xor_sync(~0u, qv, 1);
        float ko = __shfl_xor_sync(~0u, kv, 1);
        float qr = (d & 1) ? qo : -qo;
        float kr = (d & 1) ? ko : -ko;
        qv = qv * c + qr * s;
        kv = kv * c + kr * s;
    }
    size_t o = ((size_t)h * L_ + t) * HD + d;
    g_q[o] = qv; g_k[o] = kv; g_v[o] = vv;
}

// ---------------- 7: flash attention, tf32 tensor cores ----------------
// BQ=64 q-rows/block, 256 threads (8 warps). Warp w: m-tile (w&3)*16 rows,
// col-half (w>>2). QK: each warp 16x32 of S. PV: each warp 16x64 of O.
#define QSTR 132   // qs/ks stride: bank = 4q + r conflict-free for frags
#define VSTR 136   // vs stride:   bank = 8r + q
#define PSTR 68    // P stride:    bank = 4q + r
#define OFF_QS 0
#define OFF_KS (64*QSTR)
#define OFF_VS (OFF_KS + 64*QSTR)
#define OFF_ST (OFF_VS + 64*VSTR)
#define OFF_MR (OFF_ST + 64*PSTR)
#define OFF_LR (OFF_MR + 64)
#define OFF_PM (OFF_LR + 64)
#define OFF_PS (OFF_PM + 128)
#define ATTN_F (OFF_PS + 128)
#define ATTN_SMEM (ATTN_F * sizeof(float))

__global__ __launch_bounds__(256) void attn_kernel() {
    extern __shared__ float sm[];
    float* qs = sm + OFF_QS;
    float* ks = sm + OFF_KS;
    float* vs = sm + OFF_VS;
    float* st = sm + OFF_ST;
    float* mrow = sm + OFF_MR;
    float* lrow = sm + OFF_LR;
    float* pm = sm + OFF_PM;    // [2][64]
    float* ps = sm + OFF_PS;    // [2][64]

    int h  = blockIdx.y;
    int q0 = blockIdx.x * 64;
    const float* Qp = g_q + ((size_t)h * L_ + q0) * HD;
    const float* Kp = g_k + (size_t)h * L_ * HD;
    const float* Vp = g_v + (size_t)h * L_ * HD;

    int tid = threadIdx.x;
    int wid = tid >> 5, lane = tid & 31;
    int mtile = wid & 3, chalf = wid >> 2;
    int mrow0 = mtile * 16 + (lane >> 2);        // local q row (and +8)
    const float scale = 0.08838834764831845f;

    // load Q (pre-scaled, tf32)
    for (int i = tid; i < 64 * 32; i += 256) {
        int r = i >> 5, c4 = (i & 31) * 4;
        float4 v4 = *(const float4*)(Qp + (size_t)r * HD + c4);
        float4 t = make_float4(f2tf(v4.x * scale), f2tf(v4.y * scale),
                               f2tf(v4.z * scale), f2tf(v4.w * scale));
        *(float4*)&qs[r * QSTR + c4] = t;
    }
    if (tid < 64) { mrow[tid] = -1e30f; lrow[tid] = 0.f; }

    float o[8][4];
    #pragma unroll
    for (int i = 0; i < 8; i++)
        #pragma unroll
        for (int j = 0; j < 4; j++) o[i][j] = 0.f;
    __syncthreads();

    for (int k0 = 0; k0 < L_; k0 += 64) {
        // load K, V chunk
        for (int i = tid; i < 64 * 32; i += 256) {
            int r = i >> 5, c4 = (i & 31) * 4;
            float4 k4 = *(const float4*)(Kp + (size_t)(k0 + r) * HD + c4);
            float4 v4 = *(const float4*)(Vp + (size_t)(k0 + r) * HD + c4);
            float4 kt = make_float4(f2tf(k4.x), f2tf(k4.y), f2tf(k4.z), f2tf(k4.w));
            float4 vt = make_float4(f2tf(v4.x), f2tf(v4.y), f2tf(v4.z), f2tf(v4.w));
            *(float4*)&ks[r * QSTR + c4] = kt;
            *(float4*)&vs[r * VSTR + c4] = vt;
        }
        __syncthreads();

        // S = Q @ K^T : warp computes rows [mtile*16,+16) x cols [chalf*32,+32)
        float s[4][4];
        #pragma unroll
        for (int nt = 0; nt < 4; nt++)
            #pragma unroll
            for (int j = 0; j < 4; j++) s[nt][j] = 0.f;

        #pragma unroll
        for (int kk = 0; kk < 16; kk++) {
            int kr = kk * 8 + (lane & 3);
            int m0 = mtile * 16 + (lane >> 2);
            uint32_t a0 = __float_as_uint(qs[m0 * QSTR + kr]);
            uint32_t a1 = __float_as_uint(qs[(m0 + 8) * QSTR + kr]);
            uint32_t a2 = __float_as_uint(qs[m0 * QSTR + kr + 4]);
            uint32_t a3 = __float_as_uint(qs[(m0 + 8) * QSTR + kr + 4]);
            #pragma unroll
            for (int nt = 0; nt < 4; nt++) {
                int n0 = chalf * 32 + nt * 8 + (lane >> 2);
                uint32_t b0 = __float_as_uint(ks[n0 * QSTR + kr]);
                uint32_t b1 = __float_as_uint(ks[n0 * QSTR + kr + 4]);
                mma_tf32(s[nt][0], s[nt][1], s[nt][2], s[nt][3], a0, a1, a2, a3, b0, b1);
            }
        }

        // row max over this warp's 32 cols (rows mrow0, mrow0+8)
        float rmax0 = -1e30f, rmax1 = -1e30f;
        #pragma unroll
        for (int nt = 0; nt < 4; nt++) {
            rmax0 = fmaxf(rmax0, fmaxf(s[nt][0], s[nt][1]));
            rmax1 = fmaxf(rmax1, fmaxf(s[nt][2], s[nt][3]));
        }
        #pragma unroll
        for (int off = 1; off <= 2; off <<= 1) {
            rmax0 = fmaxf(rmax0, __shfl_xor_sync(~0u, rmax0, off));
            rmax1 = fmaxf(rmax1, __shfl_xor_sync(~0u, rmax1, off));
        }
        if ((lane & 3) == 0) {
            pm[chalf * 64 + mrow0] = rmax0;
            pm[chalf * 64 + mrow0 + 8] = rmax1;
        }
        __syncthreads();

        float mo0 = mrow[mrow0], mo1 = mrow[mrow0 + 8];
        float mn0 = fmaxf(mo0, fmaxf(pm[mrow0], pm[64 + mrow0]));
        float mn1 = fmaxf(mo1, fmaxf(pm[mrow0 + 8], pm[64 + mrow0 + 8]));
        float al0 = __expf(mo0 - mn0), al1 = __expf(mo1 - mn1);

        float rs0 = 0.f, rs1 = 0.f;
        #pragma unroll
        for (int nt = 0; nt < 4; nt++) {
            float p0 = __expf(s[nt][0] - mn0);
            float p1 = __expf(s[nt][1] - mn0);
            float p2 = __expf(s[nt][2] - mn1);
            float p3 = __expf(s[nt][3] - mn1);
            rs0 += p0 + p1; rs1 += p2 + p3;
            int c = chalf * 32 + nt * 8 + 2 * (lane & 3);
            *(float2*)&st[mrow0 * PSTR + c] = make_float2(f2tf(p0), f2tf(p1));
            *(float2*)&st[(mrow0 + 8) * PSTR + c] = make_float2(f2tf(p2), f2tf(p3));
        }
        #pragma unroll
        for (int off = 1; off <= 2; off <<= 1) {
            rs0 += __shfl_xor_sync(~0u, rs0, off);
            rs1 += __shfl_xor_sync(~0u, rs1, off);
        }
        if ((lane & 3) == 0) {
            ps[chalf * 64 + mrow0] = rs0;
            ps[chalf * 64 + mrow0 + 8] = rs1;
        }
        // rescale O accumulators
        #pragma unroll
        for (int nt = 0; nt < 8; nt++) {
            o[nt][0] *= al0; o[nt][1] *= al0;
            o[nt][2] *= al1; o[nt][3] *= al1;
        }
        __syncthreads();

        // update running stats (one thread per row)
        if (tid < 64) {
            float mo = mrow[tid];
            float mn = fmaxf(mo, fmaxf(pm[tid], pm[64 + tid]));
            lrow[tid] = lrow[tid] * __expf(mo - mn) + ps[tid] + ps[64 + tid];
            mrow[tid] = mn;
        }

        // O += P @ V : warp rows [mtile*16,+16) x hd cols [chalf*64,+64)
        #pragma unroll
        for (int kk = 0; kk < 8; kk++) {
            int kr = kk * 8 + (lane & 3);
            int m0 = mtile * 16 + (lane >> 2);
            uint32_t a0 = __float_as_uint(st[m0 * PSTR + kr]);
            uint32_t a1 = __float_as_uint(st[(m0 + 8) * PSTR + kr]);
            uint32_t a2 = __float_as_uint(st[m0 * PSTR + kr + 4]);
            uint32_t a3 = __float_as_uint(st[(m0 + 8) * PSTR + kr + 4]);
            #pragma unroll
            for (int nt = 0; nt < 8; nt++) {
                int n0 = chalf * 64 + nt * 8 + (lane >> 2);
                uint32_t b0 = __float_as_uint(vs[kr * VSTR + n0]);
                uint32_t b1 = __float_as_uint(vs[(kr + 4) * VSTR + n0]);
                mma_tf32(o[nt][0], o[nt][1], o[nt][2], o[nt][3], a0, a1, a2, a3, b0, b1);
            }
        }
        __syncthreads();
    }

    float inv0 = 1.f / lrow[mrow0];
    float inv1 = 1.f / lrow[mrow0 + 8];
    #pragma unroll
    for (int nt = 0; nt < 8; nt++) {
        int c = h * HD + chalf * 64 + nt * 8 + 2 * (lane & 3);
        size_t o0 = (size_t)(q0 + mrow0) * K2 + c;
        size_t o1 = (size_t)(q0 + mrow0 + 8) * K2 + c;
        *(float2*)&g_cat[o0] = make_float2(o[nt][0] * inv0, o[nt][1] * inv0);
        *(float2*)&g_cat[o1] = make_float2(o[nt][2] * inv1, o[nt][3] * inv1);
    }
}

// ---------------- launch ----------------
extern "C" void kernel_launch(void* const* d_in, const int* in_sizes, int n_in,
                              void* d_out, int out_size) {
    const float* hidden = (const float*)d_in[0];
    const float* temb   = (const float*)d_in[1];
    const float* cosb   = (const float*)d_in[2];
    const float* sinb   = (const float*)d_in[3];
    const float* ada_w  = (const float*)d_in[4];
    const float* ada_b  = (const float*)d_in[5];
    const float* lin1_w = (const float*)d_in[6];
    const float* lin1_b = (const float*)d_in[7];
    const float* lin2_w = (const float*)d_in[8];
    const float* lin2_b = (const float*)d_in[9];
    float* out = (float*)d_out;

    float *p_normx, *p_proj, *p_cat, *p_emb;
    cudaGetSymbolAddress((void**)&p_normx, g_normx);
    cudaGetSymbolAddress((void**)&p_proj,  g_proj);
    cudaGetSymbolAddress((void**)&p_cat,   g_cat);
    cudaGetSymbolAddress((void**)&p_emb,   g_emb);

    cudaFuncSetAttribute(attn_kernel,
                         cudaFuncAttributeMaxDynamicSharedMemorySize,
                         (int)ATTN_SMEM);

    silu_kernel<<<(HID + 255) / 256, 256>>>(temb);
    ada_kernel<<<(3 * HID + 255) / 256, 256>>>(ada_w, ada_b);
    ln_kernel<<<L_, 256>>>(hidden);

    // GEMM1 with split epilogue: qkv -> g_proj, gelu(mlp) -> g_cat
    tgemm_k<2><<<dim3(N1 / 128, L_ / 128), 128>>>(
        p_normx, lin1_w, lin1_b, nullptr, nullptr, p_proj, p_cat, L_, N1, HID);

    qkv_kernel<<<dim3(L_, HEADS), HD>>>(cosb, sinb,
                                        (const float*)d_in[10], (const float*)d_in[11]);
    attn_kernel<<<dim3(L_ / 64, HEADS), 256, ATTN_SMEM>>>();

    // GEMM2 with fused bias+gate+residual
    tgemm_k<1><<<dim3(HID / 128, L_ / 128), 128>>>(
        p_cat, lin2_w, lin2_b, hidden, p_emb + 2 * HID, out, nullptr, L_, HID, K2);
}

// round 4
// speedup vs baseline: 3.2653x; 1.5966x over previous
#include <cuda_runtime.h>
#include <math.h>
#include <stdint.h>

// ---------------- problem constants ----------------
#define HID   3072
#define HEADS 24
#define HD    128
#define MLP_  12288
#define L_    2304
#define TXT_  256
#define IMG   2048
#define N1    (3*HID + MLP_)      // 21504
#define K2    (HID + MLP_)        // 15360
#define QKV3  (3*HID)             // 9216

// ---------------- scratch ----------------
__device__ __align__(256) float g_silu[HID];
__device__ __align__(256) float g_emb[3*HID];
__device__ __align__(256) float g_normx[(size_t)L_*HID];
__device__ __align__(256) float g_proj[(size_t)L_*QKV3];
__device__ __align__(256) float g_q[(size_t)HEADS*L_*HD];
__device__ __align__(256) float g_k[(size_t)HEADS*L_*HD];
__device__ __align__(256) float g_v[(size_t)HEADS*L_*HD];
__device__ __align__(256) float g_cat[(size_t)L_*K2];

// ---------------- tf32 / async helpers ----------------
__device__ __forceinline__ float f2tf(float x) {
    uint32_t u;
    asm("cvt.rna.tf32.f32 %0, %1;" : "=r"(u) : "f"(x));
    return __uint_as_float(u);
}
__device__ __forceinline__ uint32_t f2tf_u(uint32_t x) {
    uint32_t u;
    asm("cvt.rna.tf32.f32 %0, %1;" : "=r"(u) : "f"(__uint_as_float(x)));
    return u;
}
__device__ __forceinline__ void mma_tf32(float& c0, float& c1, float& c2, float& c3,
                                         uint32_t a0, uint32_t a1, uint32_t a2, uint32_t a3,
                                         uint32_t b0, uint32_t b1) {
    asm volatile("mma.sync.aligned.m16n8k8.row.col.f32.tf32.tf32.f32 "
                 "{%0,%1,%2,%3}, {%4,%5,%6,%7}, {%8,%9}, {%0,%1,%2,%3};"
                 : "+f"(c0), "+f"(c1), "+f"(c2), "+f"(c3)
                 : "r"(a0), "r"(a1), "r"(a2), "r"(a3), "r"(b0), "r"(b1));
}
__device__ __forceinline__ void cp16(float* dst, const float* src) {
    uint32_t d = (uint32_t)__cvta_generic_to_shared(dst);
    asm volatile("cp.async.cg.shared.global [%0], [%1], 16;\n" :: "r"(d), "l"(src));
}
__device__ __forceinline__ void ldmx4(uint32_t* r, const float* p) {
    uint32_t a = (uint32_t)__cvta_generic_to_shared(p);
    asm volatile("ldmatrix.sync.aligned.m8n8.x4.shared.b16 {%0,%1,%2,%3}, [%4];"
                 : "=r"(r[0]), "=r"(r[1]), "=r"(r[2]), "=r"(r[3]) : "r"(a));
}
#define CP_COMMIT() asm volatile("cp.async.commit_group;\n" ::: "memory")
#define CP_WAIT2()  asm volatile("cp.async.wait_group 2;\n" ::: "memory")

// ---------------- 1: silu ----------------
__global__ void silu_kernel(const float* __restrict__ temb) {
    int i = blockIdx.x * 256 + threadIdx.x;
    if (i < HID) {
        float t = temb[i];
        g_silu[i] = t / (1.f + __expf(-t));
    }
}

// ---------------- 2: adaLN GEMV ----------------
__global__ void ada_kernel(const float* __restrict__ ada_w,
                           const float* __restrict__ ada_b) {
    int j = blockIdx.x * 256 + threadIdx.x;
    if (j >= 3*HID) return;
    float acc = 0.f;
    #pragma unroll 4
    for (int i = 0; i < HID; i++)
        acc += g_silu[i] * ada_w[(size_t)i * (3*HID) + j];
    g_emb[j] = acc + ada_b[j];
}

// ---------------- 3: layernorm + scale/shift ----------------
__global__ void ln_kernel(const float* __restrict__ x) {
    int t = blockIdx.x;
    const float* row = x + (size_t)t * HID;
    float s = 0.f, s2 = 0.f;
    for (int i = threadIdx.x; i < HID; i += 256) {
        float v = row[i];
        s += v; s2 += v * v;
    }
    #pragma unroll
    for (int o = 16; o; o >>= 1) {
        s  += __shfl_xor_sync(~0u, s,  o);
        s2 += __shfl_xor_sync(~0u, s2, o);
    }
    __shared__ float rs[8], rs2[8], smu, srinv;
    int w = threadIdx.x >> 5, lane = threadIdx.x & 31;
    if (lane == 0) { rs[w] = s; rs2[w] = s2; }
    __syncthreads();
    if (threadIdx.x == 0) {
        float a = 0.f, b = 0.f;
        #pragma unroll
        for (int i = 0; i < 8; i++) { a += rs[i]; b += rs2[i]; }
        float mu = a / HID;
        float var = b / HID - mu * mu;
        smu = mu; srinv = rsqrtf(var + 1e-6f);
    }
    __syncthreads();
    float mu = smu, rinv = srinv;
    for (int i = threadIdx.x; i < HID; i += 256) {
        float sc = 1.f + g_emb[HID + i];
        float sh = g_emb[i];
        g_normx[(size_t)t * HID + i] = (row[i] - mu) * rinv * sc + sh;
    }
}

// ---------------- tf32 GEMM: 128x128x16 tiles, cp.async 4-stage, ldmatrix A ----
// 256 threads / 8 warps (2x4 grid), warp tile 64x32.
// MODE 0: C = acc + bias
// MODE 1: C = resid + (acc + bias) * gate
// MODE 2: split: n < QKV3 -> C (stride QKV3); else gelu -> C2 (stride K2, +HID)
#define AST 20          // A smem row stride (floats): 80B, 16B aligned, LDSM conflict-free
#define BST 136         // B smem row stride
#define STAGES 4
#define A_STG (128*AST)
#define B_STG (16*BST)
#define GEMM_SMEM ((STAGES*(A_STG + B_STG)) * sizeof(float))

template<int MODE>
__global__ __launch_bounds__(256, 2) void tgemm_k(
    const float* __restrict__ A, const float* __restrict__ B,
    const float* __restrict__ bias, const float* __restrict__ resid,
    const float* __restrict__ gate,
    float* __restrict__ C, float* __restrict__ C2, int M, int N, int K)
{
    extern __shared__ float sm[];
    float* As = sm;                      // [STAGES][128][AST]
    float* Bs = sm + STAGES * A_STG;     // [STAGES][16][BST]

    int tid = threadIdx.x;
    int wid = tid >> 5, lane = tid & 31;
    int wm = wid >> 2, wn = wid & 3;     // 2x4 warp grid, 64x32 tile each
    int bm = blockIdx.y, bn = blockIdx.x;

    const float* Ab = A + (size_t)bm * 128 * K;
    const float* Bb = B + (size_t)bn * 128;

    float acc[4][4][4];
    #pragma unroll
    for (int i = 0; i < 4; i++)
        #pragma unroll
        for (int j = 0; j < 4; j++)
            #pragma unroll
            for (int q = 0; q < 4; q++) acc[i][j][q] = 0.f;

    int nkt = K / 16;

    // loader lambda-ish via macro: A 512x16B chunks, B 512x16B chunks
    #define LOAD_TILE(stg, kt_) do {                                            \
        int kg = (kt_) * 16;                                                    \
        float* as_ = As + (stg) * A_STG;                                        \
        float* bs_ = Bs + (stg) * B_STG;                                        \
        _Pragma("unroll")                                                       \
        for (int i_ = 0; i_ < 2; i_++) {                                        \
            int id = tid + i_ * 256;                                            \
            int row = id >> 2, c = (id & 3) * 4;                                \
            cp16(as_ + row * AST + c, Ab + (size_t)row * K + kg + c);           \
        }                                                                       \
        _Pragma("unroll")                                                       \
        for (int i_ = 0; i_ < 2; i_++) {                                        \
            int id = tid + i_ * 256;                                            \
            int row = id >> 5, c = (id & 31) * 4;                               \
            cp16(bs_ + row * BST + c, Bb + (size_t)(kg + row) * N + c);         \
        }                                                                       \
    } while (0)

    // prologue: stages 0..2
    #pragma unroll
    for (int s = 0; s < STAGES - 1; s++) {
        LOAD_TILE(s, s);
        CP_COMMIT();
    }

    int lrow = lane & 15;               // ldmatrix row within 16
    int lkc  = (lane >> 4) * 4;         // ldmatrix k column group

    for (int kt = 0; kt < nkt; kt++) {
        CP_WAIT2();
        __syncthreads();
        int s = kt & (STAGES - 1);
        if (kt + STAGES - 1 < nkt) {
            LOAD_TILE((kt + STAGES - 1) & (STAGES - 1), kt + STAGES - 1);
        }
        CP_COMMIT();

        const float* as_ = As + s * A_STG;
        const float* bs_ = Bs + s * B_STG;

        #pragma unroll
        for (int ks = 0; ks < 2; ks++) {
            uint32_t af[4][4], bf[4][2];
            #pragma unroll
            for (int mt = 0; mt < 4; mt++) {
                int m = wm * 64 + mt * 16 + lrow;
                ldmx4(af[mt], as_ + m * AST + ks * 8 + lkc);
                af[mt][0] = f2tf_u(af[mt][0]); af[mt][1] = f2tf_u(af[mt][1]);
                af[mt][2] = f2tf_u(af[mt][2]); af[mt][3] = f2tf_u(af[mt][3]);
            }
            int kr = ks * 8 + (lane & 3);
            #pragma unroll
            for (int nt = 0; nt < 4; nt++) {
                int n0 = wn * 32 + nt * 8 + (lane >> 2);
                bf[nt][0] = f2tf_u(__float_as_uint(bs_[kr * BST + n0]));
                bf[nt][1] = f2tf_u(__float_as_uint(bs_[(kr + 4) * BST + n0]));
            }
            #pragma unroll
            for (int mt = 0; mt < 4; mt++)
                #pragma unroll
                for (int nt = 0; nt < 4; nt++)
                    mma_tf32(acc[mt][nt][0], acc[mt][nt][1], acc[mt][nt][2], acc[mt][nt][3],
                             af[mt][0], af[mt][1], af[mt][2], af[mt][3],
                             bf[nt][0], bf[nt][1]);
        }
    }
    #undef LOAD_TILE

    // epilogue
    #pragma unroll
    for (int mt = 0; mt < 4; mt++) {
        int r0 = bm * 128 + wm * 64 + mt * 16 + (lane >> 2);
        #pragma unroll
        for (int nt = 0; nt < 4; nt++) {
            int c0 = bn * 128 + wn * 32 + nt * 8 + 2 * (lane & 3);
            float bia0 = bias[c0], bia1 = bias[c0 + 1];
            float t00 = acc[mt][nt][0] + bia0, t01 = acc[mt][nt][1] + bia1;
            float t10 = acc[mt][nt][2] + bia0, t11 = acc[mt][nt][3] + bia1;
            if (MODE == 0) {
                size_t o0 = (size_t)r0 * N + c0;
                size_t o1 = (size_t)(r0 + 8) * N + c0;
                *(float2*)(C + o0) = make_float2(t00, t01);
                *(float2*)(C + o1) = make_float2(t10, t11);
            } else if (MODE == 1) {
                size_t o0 = (size_t)r0 * N + c0;
                size_t o1 = (size_t)(r0 + 8) * N + c0;
                float gg0 = gate[c0], gg1 = gate[c0 + 1];
                float2 r_0 = *(const float2*)(resid + o0);
                float2 r_1 = *(const float2*)(resid + o1);
                *(float2*)(C + o0) = make_float2(r_0.x + t00 * gg0, r_0.y + t01 * gg1);
                *(float2*)(C + o1) = make_float2(r_1.x + t10 * gg0, r_1.y + t11 * gg1);
            } else {
                if (c0 < QKV3) {
                    size_t o0 = (size_t)r0 * QKV3 + c0;
                    size_t o1 = (size_t)(r0 + 8) * QKV3 + c0;
                    *(float2*)(C + o0) = make_float2(t00, t01);
                    *(float2*)(C + o1) = make_float2(t10, t11);
                } else {
                    int cc = c0 - QKV3;
                    size_t o0 = (size_t)r0 * K2 + HID + cc;
                    size_t o1 = (size_t)(r0 + 8) * K2 + HID + cc;
                    const float kA = 0.7978845608028654f, kB = 0.044715f;
                    float g00 = 0.5f * t00 * (1.f + tanhf(kA * (t00 + kB * t00 * t00 * t00)));
                    float g01 = 0.5f * t01 * (1.f + tanhf(kA * (t01 + kB * t01 * t01 * t01)));
                    float g10 = 0.5f * t10 * (1.f + tanhf(kA * (t10 + kB * t10 * t10 * t10)));
                    float g11 = 0.5f * t11 * (1.f + tanhf(kA * (t11 + kB * t11 * t11 * t11)));
                    *(float2*)(C2 + o0) = make_float2(g00, g01);
                    *(float2*)(C2 + o1) = make_float2(g10, g11);
                }
            }
        }
    }
}

// ---------------- 5: qkv split + rmsnorm + rope ----------------
__global__ void qkv_kernel(const float* __restrict__ cosb, const float* __restrict__ sinb,
                           const float* __restrict__ qn,   const float* __restrict__ kn) {
    int t = blockIdx.x, h = blockIdx.y, d = threadIdx.x;
    const float* p = g_proj + (size_t)t * QKV3 + h * HD + d;
    float qv = p[0], kv = p[HID], vv = p[2*HID];

    float sq = qv * qv, sk = kv * kv;
    #pragma unroll
    for (int o = 16; o; o >>= 1) {
        sq += __shfl_xor_sync(~0u, sq, o);
        sk += __shfl_xor_sync(~0u, sk, o);
    }
    __shared__ float rq[4], rk[4];
    int w = d >> 5;
    if ((d & 31) == 0) { rq[w] = sq; rk[w] = sk; }
    __syncthreads();
    sq = rq[0] + rq[1] + rq[2] + rq[3];
    sk = rk[0] + rk[1] + rk[2] + rk[3];
    qv = qv * rsqrtf(sq / HD + 1e-6f) * qn[d];
    kv = kv * rsqrtf(sk / HD + 1e-6f) * kn[d];

    if (t < IMG) {
        float c = cosb[(size_t)t * HD + d];
        float s = sinb[(size_t)t * HD + d];
        float qo = __shfl_xor_sync(~0u, qv, 1);
        float ko = __shfl_xor_sync(~0u, kv, 1);
        float qr = (d & 1) ? qo : -qo;
        float kr = (d & 1) ? ko : -ko;
        qv = qv * c + qr * s;
        kv = kv * c + kr * s;
    }
    size_t o = ((size_t)h * L_ + t) * HD + d;
    g_q[o] = qv; g_k[o] = kv; g_v[o] = vv;
}

// ---------------- 7: flash attention, tf32 tensor cores ----------------
#define QSTR 132
#define VSTR 136
#define PSTR 68
#define OFF_QS 0
#define OFF_KS (64*QSTR)
#define OFF_VS (OFF_KS + 64*QSTR)
#define OFF_ST (OFF_VS + 64*VSTR)
#define OFF_MR (OFF_ST + 64*PSTR)
#define OFF_LR (OFF_MR + 64)
#define OFF_PM (OFF_LR + 64)
#define OFF_PS (OFF_PM + 128)
#define ATTN_F (OFF_PS + 128)
#define ATTN_SMEM (ATTN_F * sizeof(float))

__global__ __launch_bounds__(256) void attn_kernel() {
    extern __shared__ float smf[];
    float* qs = smf + OFF_QS;
    float* ks = smf + OFF_KS;
    float* vs = smf + OFF_VS;
    float* st = smf + OFF_ST;
    float* mrow = smf + OFF_MR;
    float* lrow = smf + OFF_LR;
    float* pm = smf + OFF_PM;
    float* ps = smf + OFF_PS;

    int h  = blockIdx.y;
    int q0 = blockIdx.x * 64;
    const float* Qp = g_q + ((size_t)h * L_ + q0) * HD;
    const float* Kp = g_k + (size_t)h * L_ * HD;
    const float* Vp = g_v + (size_t)h * L_ * HD;

    int tid = threadIdx.x;
    int wid = tid >> 5, lane = tid & 31;
    int mtile = wid & 3, chalf = wid >> 2;
    int mrow0 = mtile * 16 + (lane >> 2);
    const float scale = 0.08838834764831845f;

    for (int i = tid; i < 64 * 32; i += 256) {
        int r = i >> 5, c4 = (i & 31) * 4;
        float4 v4 = *(const float4*)(Qp + (size_t)r * HD + c4);
        float4 t = make_float4(f2tf(v4.x * scale), f2tf(v4.y * scale),
                               f2tf(v4.z * scale), f2tf(v4.w * scale));
        *(float4*)&qs[r * QSTR + c4] = t;
    }
    if (tid < 64) { mrow[tid] = -1e30f; lrow[tid] = 0.f; }

    float o[8][4];
    #pragma unroll
    for (int i = 0; i < 8; i++)
        #pragma unroll
        for (int j = 0; j < 4; j++) o[i][j] = 0.f;
    __syncthreads();

    for (int k0 = 0; k0 < L_; k0 += 64) {
        for (int i = tid; i < 64 * 32; i += 256) {
            int r = i >> 5, c4 = (i & 31) * 4;
            float4 k4 = *(const float4*)(Kp + (size_t)(k0 + r) * HD + c4);
            float4 v4 = *(const float4*)(Vp + (size_t)(k0 + r) * HD + c4);
            float4 kt = make_float4(f2tf(k4.x), f2tf(k4.y), f2tf(k4.z), f2tf(k4.w));
            float4 vt = make_float4(f2tf(v4.x), f2tf(v4.y), f2tf(v4.z), f2tf(v4.w));
            *(float4*)&ks[r * QSTR + c4] = kt;
            *(float4*)&vs[r * VSTR + c4] = vt;
        }
        __syncthreads();

        float s[4][4];
        #pragma unroll
        for (int nt = 0; nt < 4; nt++)
            #pragma unroll
            for (int j = 0; j < 4; j++) s[nt][j] = 0.f;

        #pragma unroll
        for (int kk = 0; kk < 16; kk++) {
            int kr = kk * 8 + (lane & 3);
            int m0 = mtile * 16 + (lane >> 2);
            uint32_t a0 = __float_as_uint(qs[m0 * QSTR + kr]);
            uint32_t a1 = __float_as_uint(qs[(m0 + 8) * QSTR + kr]);
            uint32_t a2 = __float_as_uint(qs[m0 * QSTR + kr + 4]);
            uint32_t a3 = __float_as_uint(qs[(m0 + 8) * QSTR + kr + 4]);
            #pragma unroll
            for (int nt = 0; nt < 4; nt++) {
                int n0 = chalf * 32 + nt * 8 + (lane >> 2);
                uint32_t b0 = __float_as_uint(ks[n0 * QSTR + kr]);
                uint32_t b1 = __float_as_uint(ks[n0 * QSTR + kr + 4]);
                mma_tf32(s[nt][0], s[nt][1], s[nt][2], s[nt][3], a0, a1, a2, a3, b0, b1);
            }
        }

        float rmax0 = -1e30f, rmax1 = -1e30f;
        #pragma unroll
        for (int nt = 0; nt < 4; nt++) {
            rmax0 = fmaxf(rmax0, fmaxf(s[nt][0], s[nt][1]));
            rmax1 = fmaxf(rmax1, fmaxf(s[nt][2], s[nt][3]));
        }
        #pragma unroll
        for (int off = 1; off <= 2; off <<= 1) {
            rmax0 = fmaxf(rmax0, __shfl_xor_sync(~0u, rmax0, off));
            rmax1 = fmaxf(rmax1, __shfl_xor_sync(~0u, rmax1, off));
        }
        if ((lane & 3) == 0) {
            pm[chalf * 64 + mrow0] = rmax0;
            pm[chalf * 64 + mrow0 + 8] = rmax1;
        }
        __syncthreads();

        float mo0 = mrow[mrow0], mo1 = mrow[mrow0 + 8];
        float mn0 = fmaxf(mo0, fmaxf(pm[mrow0], pm[64 + mrow0]));
        float mn1 = fmaxf(mo1, fmaxf(pm[mrow0 + 8], pm[64 + mrow0 + 8]));
        float al0 = __expf(mo0 - mn0), al1 = __expf(mo1 - mn1);

        float rs0 = 0.f, rs1 = 0.f;
        #pragma unroll
        for (int nt = 0; nt < 4; nt++) {
            float p0 = __expf(s[nt][0] - mn0);
            float p1 = __expf(s[nt][1] - mn0);
            float p2 = __expf(s[nt][2] - mn1);
            float p3 = __expf(s[nt][3] - mn1);
            rs0 += p0 + p1; rs1 += p2 + p3;
            int c = chalf * 32 + nt * 8 + 2 * (lane & 3);
            *(float2*)&st[mrow0 * PSTR + c] = make_float2(f2tf(p0), f2tf(p1));
            *(float2*)&st[(mrow0 + 8) * PSTR + c] = make_float2(f2tf(p2), f2tf(p3));
        }
        #pragma unroll
        for (int off = 1; off <= 2; off <<= 1) {
            rs0 += __shfl_xor_sync(~0u, rs0, off);
            rs1 += __shfl_xor_sync(~0u, rs1, off);
        }
        if ((lane & 3) == 0) {
            ps[chalf * 64 + mrow0] = rs0;
            ps[chalf * 64 + mrow0 + 8] = rs1;
        }
        #pragma unroll
        for (int nt = 0; nt < 8; nt++) {
            o[nt][0] *= al0; o[nt][1] *= al0;
            o[nt][2] *= al1; o[nt][3] *= al1;
        }
        __syncthreads();

        if (tid < 64) {
            float mo = mrow[tid];
            float mn = fmaxf(mo, fmaxf(pm[tid], pm[64 + tid]));
            lrow[tid] = lrow[tid] * __expf(mo - mn) + ps[tid] + ps[64 + tid];
            mrow[tid] = mn;
        }

        #pragma unroll
        for (int kk = 0; kk < 8; kk++) {
            int kr = kk * 8 + (lane & 3);
            int m0 = mtile * 16 + (lane >> 2);
            uint32_t a0 = __float_as_uint(st[m0 * PSTR + kr]);
            uint32_t a1 = __float_as_uint(st[(m0 + 8) * PSTR + kr]);
            uint32_t a2 = __float_as_uint(st[m0 * PSTR + kr + 4]);
            uint32_t a3 = __float_as_uint(st[(m0 + 8) * PSTR + kr + 4]);
            #pragma unroll
            for (int nt = 0; nt < 8; nt++) {
                int n0 = chalf * 64 + nt * 8 + (lane >> 2);
                uint32_t b0 = __float_as_uint(vs[kr * VSTR + n0]);
                uint32_t b1 = __float_as_uint(vs[(kr + 4) * VSTR + n0]);
                mma_tf32(o[nt][0], o[nt][1], o[nt][2], o[nt][3], a0, a1, a2, a3, b0, b1);
            }
        }
        __syncthreads();
    }

    float inv0 = 1.f / lrow[mrow0];
    float inv1 = 1.f / lrow[mrow0 + 8];
    #pragma unroll
    for (int nt = 0; nt < 8; nt++) {
        int c = h * HD + chalf * 64 + nt * 8 + 2 * (lane & 3);
        size_t o0 = (size_t)(q0 + mrow0) * K2 + c;
        size_t o1 = (size_t)(q0 + mrow0 + 8) * K2 + c;
        *(float2*)&g_cat[o0] = make_float2(o[nt][0] * inv0, o[nt][1] * inv0);
        *(float2*)&g_cat[o1] = make_float2(o[nt][2] * inv1, o[nt][3] * inv1);
    }
}

// ---------------- launch ----------------
extern "C" void kernel_launch(void* const* d_in, const int* in_sizes, int n_in,
                              void* d_out, int out_size) {
    const float* hidden = (const float*)d_in[0];
    const float* temb   = (const float*)d_in[1];
    const float* cosb   = (const float*)d_in[2];
    const float* sinb   = (const float*)d_in[3];
    const float* ada_w  = (const float*)d_in[4];
    const float* ada_b  = (const float*)d_in[5];
    const float* lin1_w = (const float*)d_in[6];
    const float* lin1_b = (const float*)d_in[7];
    const float* lin2_w = (const float*)d_in[8];
    const float* lin2_b = (const float*)d_in[9];
    float* out = (float*)d_out;

    float *p_normx, *p_proj, *p_cat, *p_emb;
    cudaGetSymbolAddress((void**)&p_normx, g_normx);
    cudaGetSymbolAddress((void**)&p_proj,  g_proj);
    cudaGetSymbolAddress((void**)&p_cat,   g_cat);
    cudaGetSymbolAddress((void**)&p_emb,   g_emb);

    cudaFuncSetAttribute(attn_kernel,
                         cudaFuncAttributeMaxDynamicSharedMemorySize, (int)ATTN_SMEM);
    cudaFuncSetAttribute(tgemm_k<1>,
                         cudaFuncAttributeMaxDynamicSharedMemorySize, (int)GEMM_SMEM);
    cudaFuncSetAttribute(tgemm_k<2>,
                         cudaFuncAttributeMaxDynamicSharedMemorySize, (int)GEMM_SMEM);

    silu_kernel<<<(HID + 255) / 256, 256>>>(temb);
    ada_kernel<<<(3 * HID + 255) / 256, 256>>>(ada_w, ada_b);
    ln_kernel<<<L_, 256>>>(hidden);

    // GEMM1 with split epilogue: qkv -> g_proj, gelu(mlp) -> g_cat
    tgemm_k<2><<<dim3(N1 / 128, L_ / 128), 256, GEMM_SMEM>>>(
        p_normx, lin1_w, lin1_b, nullptr, nullptr, p_proj, p_cat, L_, N1, HID);

    qkv_kernel<<<dim3(L_, HEADS), HD>>>(cosb, sinb,
                                        (const float*)d_in[10], (const float*)d_in[11]);
    attn_kernel<<<dim3(L_ / 64, HEADS), 256, ATTN_SMEM>>>();

    // GEMM2 with fused bias+gate+residual
    tgemm_k<1><<<dim3(HID / 128, L_ / 128), 256, GEMM_SMEM>>>(
        p_cat, lin2_w, lin2_b, hidden, p_emb + 2 * HID, out, nullptr, L_, HID, K2);
}

// round 5
// speedup vs baseline: 3.6578x; 1.1202x over previous
#include <cuda_runtime.h>
#include <math.h>
#include <stdint.h>

// ---------------- problem constants ----------------
#define HID   3072
#define HEADS 24
#define HD    128
#define MLP_  12288
#define L_    2304
#define TXT_  256
#define IMG   2048
#define N1    (3*HID + MLP_)      // 21504
#define K2    (HID + MLP_)        // 15360
#define QKV3  (3*HID)             // 9216

// ---------------- scratch ----------------
__device__ __align__(256) float g_silu[HID];
__device__ __align__(256) float g_emb[3*HID];
__device__ __align__(256) float g_normx[(size_t)L_*HID];
__device__ __align__(256) float g_proj[(size_t)L_*QKV3];
__device__ __align__(256) float g_q[(size_t)HEADS*L_*HD];
__device__ __align__(256) float g_k[(size_t)HEADS*L_*HD];
__device__ __align__(256) float g_v[(size_t)HEADS*L_*HD];
__device__ __align__(256) float g_cat[(size_t)L_*K2];
__device__ __align__(256) float g_w1t[(size_t)HID*N1];     // tf32-rounded lin1_w
__device__ __align__(256) float g_w2t[(size_t)K2*HID];     // tf32-rounded lin2_w

// ---------------- tf32 / async helpers ----------------
__device__ __forceinline__ float f2tf(float x) {
    uint32_t u;
    asm("cvt.rna.tf32.f32 %0, %1;" : "=r"(u) : "f"(x));
    return __uint_as_float(u);
}
__device__ __forceinline__ void mma_tf32(float& c0, float& c1, float& c2, float& c3,
                                         uint32_t a0, uint32_t a1, uint32_t a2, uint32_t a3,
                                         uint32_t b0, uint32_t b1) {
    asm volatile("mma.sync.aligned.m16n8k8.row.col.f32.tf32.tf32.f32 "
                 "{%0,%1,%2,%3}, {%4,%5,%6,%7}, {%8,%9}, {%0,%1,%2,%3};"
                 : "+f"(c0), "+f"(c1), "+f"(c2), "+f"(c3)
                 : "r"(a0), "r"(a1), "r"(a2), "r"(a3), "r"(b0), "r"(b1));
}
__device__ __forceinline__ void cp16(float* dst, const float* src) {
    uint32_t d = (uint32_t)__cvta_generic_to_shared(dst);
    asm volatile("cp.async.cg.shared.global [%0], [%1], 16;\n" :: "r"(d), "l"(src));
}
__device__ __forceinline__ void ldmx4(uint32_t* r, const float* p) {
    uint32_t a = (uint32_t)__cvta_generic_to_shared(p);
    asm volatile("ldmatrix.sync.aligned.m8n8.x4.shared.b16 {%0,%1,%2,%3}, [%4];"
                 : "=r"(r[0]), "=r"(r[1]), "=r"(r[2]), "=r"(r[3]) : "r"(a));
}
#define CP_COMMIT() asm volatile("cp.async.commit_group;\n" ::: "memory")
#define CP_WAIT2()  asm volatile("cp.async.wait_group 2;\n" ::: "memory")

// ---------------- 0: weight rounding ----------------
__global__ void wround_kernel(const float* __restrict__ w, float* __restrict__ o, int n4) {
    int i = blockIdx.x * 256 + threadIdx.x;
    if (i < n4) {
        float4 v = ((const float4*)w)[i];
        float4 t = make_float4(f2tf(v.x), f2tf(v.y), f2tf(v.z), f2tf(v.w));
        ((float4*)o)[i] = t;
    }
}

// ---------------- 1: silu ----------------
__global__ void silu_kernel(const float* __restrict__ temb) {
    int i = blockIdx.x * 256 + threadIdx.x;
    if (i < HID) {
        float t = temb[i];
        g_silu[i] = t / (1.f + __expf(-t));
    }
}

// ---------------- 2: adaLN GEMV ----------------
__global__ void ada_kernel(const float* __restrict__ ada_w,
                           const float* __restrict__ ada_b) {
    int j = blockIdx.x * 256 + threadIdx.x;
    if (j >= 3*HID) return;
    float acc = 0.f;
    #pragma unroll 4
    for (int i = 0; i < HID; i++)
        acc += g_silu[i] * ada_w[(size_t)i * (3*HID) + j];
    g_emb[j] = acc + ada_b[j];
}

// ---------------- 3: layernorm + scale/shift (writes tf32-rounded) ----------------
__global__ void ln_kernel(const float* __restrict__ x) {
    int t = blockIdx.x;
    const float* row = x + (size_t)t * HID;
    float s = 0.f, s2 = 0.f;
    for (int i = threadIdx.x; i < HID; i += 256) {
        float v = row[i];
        s += v; s2 += v * v;
    }
    #pragma unroll
    for (int o = 16; o; o >>= 1) {
        s  += __shfl_xor_sync(~0u, s,  o);
        s2 += __shfl_xor_sync(~0u, s2, o);
    }
    __shared__ float rs[8], rs2[8], smu, srinv;
    int w = threadIdx.x >> 5, lane = threadIdx.x & 31;
    if (lane == 0) { rs[w] = s; rs2[w] = s2; }
    __syncthreads();
    if (threadIdx.x == 0) {
        float a = 0.f, b = 0.f;
        #pragma unroll
        for (int i = 0; i < 8; i++) { a += rs[i]; b += rs2[i]; }
        float mu = a / HID;
        float var = b / HID - mu * mu;
        smu = mu; srinv = rsqrtf(var + 1e-6f);
    }
    __syncthreads();
    float mu = smu, rinv = srinv;
    for (int i = threadIdx.x; i < HID; i += 256) {
        float sc = 1.f + g_emb[HID + i];
        float sh = g_emb[i];
        g_normx[(size_t)t * HID + i] = f2tf((row[i] - mu) * rinv * sc + sh);
    }
}

// ---------------- tf32 GEMM: 128x128x16 tiles, cp.async 4-stage, ldmatrix A ----
// Operands pre-rounded to tf32 -> no cvt in mainloop.
// MODE 1: C = resid + (acc + bias) * gate
// MODE 2: split: n < QKV3 -> C (fp32, stride QKV3); else gelu -> C2 (tf32, stride K2, +HID)
#define AST 20
#define BST 136
#define STAGES 4
#define A_STG (128*AST)
#define B_STG (16*BST)
#define GEMM_SMEM ((STAGES*(A_STG + B_STG)) * sizeof(float))

template<int MODE>
__global__ __launch_bounds__(256, 2) void tgemm_k(
    const float* __restrict__ A, const float* __restrict__ B,
    const float* __restrict__ bias, const float* __restrict__ resid,
    const float* __restrict__ gate,
    float* __restrict__ C, float* __restrict__ C2, int M, int N, int K)
{
    extern __shared__ float sm[];
    float* As = sm;
    float* Bs = sm + STAGES * A_STG;

    int tid = threadIdx.x;
    int wid = tid >> 5, lane = tid & 31;
    int wm = wid >> 2, wn = wid & 3;
    int bm = blockIdx.y, bn = blockIdx.x;

    const float* Ab = A + (size_t)bm * 128 * K;
    const float* Bb = B + (size_t)bn * 128;

    float acc[4][4][4];
    #pragma unroll
    for (int i = 0; i < 4; i++)
        #pragma unroll
        for (int j = 0; j < 4; j++)
            #pragma unroll
            for (int q = 0; q < 4; q++) acc[i][j][q] = 0.f;

    int nkt = K / 16;

    #define LOAD_TILE(stg, kt_) do {                                            \
        int kg = (kt_) * 16;                                                    \
        float* as_ = As + (stg) * A_STG;                                        \
        float* bs_ = Bs + (stg) * B_STG;                                        \
        _Pragma("unroll")                                                       \
        for (int i_ = 0; i_ < 2; i_++) {                                        \
            int id = tid + i_ * 256;                                            \
            int row = id >> 2, c = (id & 3) * 4;                                \
            cp16(as_ + row * AST + c, Ab + (size_t)row * K + kg + c);           \
        }                                                                       \
        _Pragma("unroll")                                                       \
        for (int i_ = 0; i_ < 2; i_++) {                                        \
            int id = tid + i_ * 256;                                            \
            int row = id >> 5, c = (id & 31) * 4;                               \
            cp16(bs_ + row * BST + c, Bb + (size_t)(kg + row) * N + c);         \
        }                                                                       \
    } while (0)

    #pragma unroll
    for (int s = 0; s < STAGES - 1; s++) {
        LOAD_TILE(s, s);
        CP_COMMIT();
    }

    int lrow = lane & 15;
    int lkc  = (lane >> 4) * 4;

    for (int kt = 0; kt < nkt; kt++) {
        CP_WAIT2();
        __syncthreads();
        int s = kt & (STAGES - 1);
        if (kt + STAGES - 1 < nkt) {
            LOAD_TILE((kt + STAGES - 1) & (STAGES - 1), kt + STAGES - 1);
        }
        CP_COMMIT();

        const float* as_ = As + s * A_STG;
        const float* bs_ = Bs + s * B_STG;

        #pragma unroll
        for (int ks = 0; ks < 2; ks++) {
            uint32_t af[4][4], bf[4][2];
            #pragma unroll
            for (int mt = 0; mt < 4; mt++) {
                int m = wm * 64 + mt * 16 + lrow;
                ldmx4(af[mt], as_ + m * AST + ks * 8 + lkc);
            }
            int kr = ks * 8 + (lane & 3);
            #pragma unroll
            for (int nt = 0; nt < 4; nt++) {
                int n0 = wn * 32 + nt * 8 + (lane >> 2);
                bf[nt][0] = __float_as_uint(bs_[kr * BST + n0]);
                bf[nt][1] = __float_as_uint(bs_[(kr + 4) * BST + n0]);
            }
            #pragma unroll
            for (int mt = 0; mt < 4; mt++)
                #pragma unroll
                for (int nt = 0; nt < 4; nt++)
                    mma_tf32(acc[mt][nt][0], acc[mt][nt][1], acc[mt][nt][2], acc[mt][nt][3],
                             af[mt][0], af[mt][1], af[mt][2], af[mt][3],
                             bf[nt][0], bf[nt][1]);
        }
    }
    #undef LOAD_TILE

    #pragma unroll
    for (int mt = 0; mt < 4; mt++) {
        int r0 = bm * 128 + wm * 64 + mt * 16 + (lane >> 2);
        #pragma unroll
        for (int nt = 0; nt < 4; nt++) {
            int c0 = bn * 128 + wn * 32 + nt * 8 + 2 * (lane & 3);
            float bia0 = bias[c0], bia1 = bias[c0 + 1];
            float t00 = acc[mt][nt][0] + bia0, t01 = acc[mt][nt][1] + bia1;
            float t10 = acc[mt][nt][2] + bia0, t11 = acc[mt][nt][3] + bia1;
            if (MODE == 1) {
                size_t o0 = (size_t)r0 * N + c0;
                size_t o1 = (size_t)(r0 + 8) * N + c0;
                float gg0 = gate[c0], gg1 = gate[c0 + 1];
                float2 r_0 = *(const float2*)(resid + o0);
                float2 r_1 = *(const float2*)(resid + o1);
                *(float2*)(C + o0) = make_float2(r_0.x + t00 * gg0, r_0.y + t01 * gg1);
                *(float2*)(C + o1) = make_float2(r_1.x + t10 * gg0, r_1.y + t11 * gg1);
            } else {
                if (c0 < QKV3) {
                    size_t o0 = (size_t)r0 * QKV3 + c0;
                    size_t o1 = (size_t)(r0 + 8) * QKV3 + c0;
                    *(float2*)(C + o0) = make_float2(t00, t01);
                    *(float2*)(C + o1) = make_float2(t10, t11);
                } else {
                    int cc = c0 - QKV3;
                    size_t o0 = (size_t)r0 * K2 + HID + cc;
                    size_t o1 = (size_t)(r0 + 8) * K2 + HID + cc;
                    const float kA = 0.7978845608028654f, kB = 0.044715f;
                    float g00 = 0.5f * t00 * (1.f + tanhf(kA * (t00 + kB * t00 * t00 * t00)));
                    float g01 = 0.5f * t01 * (1.f + tanhf(kA * (t01 + kB * t01 * t01 * t01)));
                    float g10 = 0.5f * t10 * (1.f + tanhf(kA * (t10 + kB * t10 * t10 * t10)));
                    float g11 = 0.5f * t11 * (1.f + tanhf(kA * (t11 + kB * t11 * t11 * t11)));
                    *(float2*)(C2 + o0) = make_float2(f2tf(g00), f2tf(g01));
                    *(float2*)(C2 + o1) = make_float2(f2tf(g10), f2tf(g11));
                }
            }
        }
    }
}

// ---------------- 5: qkv split + rmsnorm + rope (writes tf32-rounded, q pre-scaled) --
__global__ void qkv_kernel(const float* __restrict__ cosb, const float* __restrict__ sinb,
                           const float* __restrict__ qn,   const float* __restrict__ kn) {
    int t = blockIdx.x, h = blockIdx.y, d = threadIdx.x;
    const float* p = g_proj + (size_t)t * QKV3 + h * HD + d;
    float qv = p[0], kv = p[HID], vv = p[2*HID];

    float sq = qv * qv, sk = kv * kv;
    #pragma unroll
    for (int o = 16; o; o >>= 1) {
        sq += __shfl_xor_sync(~0u, sq, o);
        sk += __shfl_xor_sync(~0u, sk, o);
    }
    __shared__ float rq[4], rk[4];
    int w = d >> 5;
    if ((d & 31) == 0) { rq[w] = sq; rk[w] = sk; }
    __syncthreads();
    sq = rq[0] + rq[1] + rq[2] + rq[3];
    sk = rk[0] + rk[1] + rk[2] + rk[3];
    qv = qv * rsqrtf(sq / HD + 1e-6f) * qn[d];
    kv = kv * rsqrtf(sk / HD + 1e-6f) * kn[d];

    if (t < IMG) {
        float c = cosb[(size_t)t * HD + d];
        float s = sinb[(size_t)t * HD + d];
        float qo = __shfl_xor_sync(~0u, qv, 1);
        float ko = __shfl_xor_sync(~0u, kv, 1);
        float qr = (d & 1) ? qo : -qo;
        float kr = (d & 1) ? ko : -ko;
        qv = qv * c + qr * s;
        kv = kv * c + kr * s;
    }
    const float scale = 0.08838834764831845f;  // 1/sqrt(128)
    size_t o = ((size_t)h * L_ + t) * HD + d;
    g_q[o] = f2tf(qv * scale);
    g_k[o] = f2tf(kv);
    g_v[o] = f2tf(vv);
}

// ---------------- 7: flash attention, tf32 tensor cores ----------------
#define QSTR 132
#define VSTR 136
#define PSTR 68
#define OFF_QS 0
#define OFF_KS (64*QSTR)
#define OFF_VS (OFF_KS + 64*QSTR)
#define OFF_ST (OFF_VS + 64*VSTR)
#define OFF_MR (OFF_ST + 64*PSTR)
#define OFF_LR (OFF_MR + 64)
#define OFF_PM (OFF_LR + 64)
#define OFF_PS (OFF_PM + 128)
#define ATTN_F (OFF_PS + 128)
#define ATTN_SMEM (ATTN_F * sizeof(float))

__global__ __launch_bounds__(256) void attn_kernel() {
    extern __shared__ float smf[];
    float* qs = smf + OFF_QS;
    float* ks = smf + OFF_KS;
    float* vs = smf + OFF_VS;
    float* st = smf + OFF_ST;
    float* mrow = smf + OFF_MR;
    float* lrow = smf + OFF_LR;
    float* pm = smf + OFF_PM;
    float* ps = smf + OFF_PS;

    int h  = blockIdx.y;
    int q0 = blockIdx.x * 64;
    const float* Qp = g_q + ((size_t)h * L_ + q0) * HD;
    const float* Kp = g_k + (size_t)h * L_ * HD;
    const float* Vp = g_v + (size_t)h * L_ * HD;

    int tid = threadIdx.x;
    int wid = tid >> 5, lane = tid & 31;
    int mtile = wid & 3, chalf = wid >> 2;
    int mrow0 = mtile * 16 + (lane >> 2);

    for (int i = tid; i < 64 * 32; i += 256) {
        int r = i >> 5, c4 = (i & 31) * 4;
        *(float4*)&qs[r * QSTR + c4] = *(const float4*)(Qp + (size_t)r * HD + c4);
    }
    if (tid < 64) { mrow[tid] = -1e30f; lrow[tid] = 0.f; }

    float o[8][4];
    #pragma unroll
    for (int i = 0; i < 8; i++)
        #pragma unroll
        for (int j = 0; j < 4; j++) o[i][j] = 0.f;
    __syncthreads();

    for (int k0 = 0; k0 < L_; k0 += 64) {
        for (int i = tid; i < 64 * 32; i += 256) {
            int r = i >> 5, c4 = (i & 31) * 4;
            *(float4*)&ks[r * QSTR + c4] = *(const float4*)(Kp + (size_t)(k0 + r) * HD + c4);
            *(float4*)&vs[r * VSTR + c4] = *(const float4*)(Vp + (size_t)(k0 + r) * HD + c4);
        }
        __syncthreads();

        float s[4][4];
        #pragma unroll
        for (int nt = 0; nt < 4; nt++)
            #pragma unroll
            for (int j = 0; j < 4; j++) s[nt][j] = 0.f;

        #pragma unroll
        for (int kk = 0; kk < 16; kk++) {
            int kr = kk * 8 + (lane & 3);
            int m0 = mtile * 16 + (lane >> 2);
            uint32_t a0 = __float_as_uint(qs[m0 * QSTR + kr]);
            uint32_t a1 = __float_as_uint(qs[(m0 + 8) * QSTR + kr]);
            uint32_t a2 = __float_as_uint(qs[m0 * QSTR + kr + 4]);
            uint32_t a3 = __float_as_uint(qs[(m0 + 8) * QSTR + kr + 4]);
            #pragma unroll
            for (int nt = 0; nt < 4; nt++) {
                int n0 = chalf * 32 + nt * 8 + (lane >> 2);
                uint32_t b0 = __float_as_uint(ks[n0 * QSTR + kr]);
                uint32_t b1 = __float_as_uint(ks[n0 * QSTR + kr + 4]);
                mma_tf32(s[nt][0], s[nt][1], s[nt][2], s[nt][3], a0, a1, a2, a3, b0, b1);
            }
        }

        float rmax0 = -1e30f, rmax1 = -1e30f;
        #pragma unroll
        for (int nt = 0; nt < 4; nt++) {
            rmax0 = fmaxf(rmax0, fmaxf(s[nt][0], s[nt][1]));
            rmax1 = fmaxf(rmax1, fmaxf(s[nt][2], s[nt][3]));
        }
        #pragma unroll
        for (int off = 1; off <= 2; off <<= 1) {
            rmax0 = fmaxf(rmax0, __shfl_xor_sync(~0u, rmax0, off));
            rmax1 = fmaxf(rmax1, __shfl_xor_sync(~0u, rmax1, off));
        }
        if ((lane & 3) == 0) {
            pm[chalf * 64 + mrow0] = rmax0;
            pm[chalf * 64 + mrow0 + 8] = rmax1;
        }
        __syncthreads();

        float mo0 = mrow[mrow0], mo1 = mrow[mrow0 + 8];
        float mn0 = fmaxf(mo0, fmaxf(pm[mrow0], pm[64 + mrow0]));
        float mn1 = fmaxf(mo1, fmaxf(pm[mrow0 + 8], pm[64 + mrow0 + 8]));
        float al0 = __expf(mo0 - mn0), al1 = __expf(mo1 - mn1);

        float rs0 = 0.f, rs1 = 0.f;
        #pragma unroll
        for (int nt = 0; nt < 4; nt++) {
            float p0 = __expf(s[nt][0] - mn0);
            float p1 = __expf(s[nt][1] - mn0);
            float p2 = __expf(s[nt][2] - mn1);
            float p3 = __expf(s[nt][3] - mn1);
            rs0 += p0 + p1; rs1 += p2 + p3;
            int c = chalf * 32 + nt * 8 + 2 * (lane & 3);
            *(float2*)&st[mrow0 * PSTR + c] = make_float2(f2tf(p0), f2tf(p1));
            *(float2*)&st[(mrow0 + 8) * PSTR + c] = make_float2(f2tf(p2), f2tf(p3));
        }
        #pragma unroll
        for (int off = 1; off <= 2; off <<= 1) {
            rs0 += __shfl_xor_sync(~0u, rs0, off);
            rs1 += __shfl_xor_sync(~0u, rs1, off);
        }
        if ((lane & 3) == 0) {
            ps[chalf * 64 + mrow0] = rs0;
            ps[chalf * 64 + mrow0 + 8] = rs1;
        }
        #pragma unroll
        for (int nt = 0; nt < 8; nt++) {
            o[nt][0] *= al0; o[nt][1] *= al0;
            o[nt][2] *= al1; o[nt][3] *= al1;
        }
        __syncthreads();

        if (tid < 64) {
            float mo = mrow[tid];
            float mn = fmaxf(mo, fmaxf(pm[tid], pm[64 + tid]));
            lrow[tid] = lrow[tid] * __expf(mo - mn) + ps[tid] + ps[64 + tid];
            mrow[tid] = mn;
        }

        #pragma unroll
        for (int kk = 0; kk < 8; kk++) {
            int kr = kk * 8 + (lane & 3);
            int m0 = mtile * 16 + (lane >> 2);
            uint32_t a0 = __float_as_uint(st[m0 * PSTR + kr]);
            uint32_t a1 = __float_as_uint(st[(m0 + 8) * PSTR + kr]);
            uint32_t a2 = __float_as_uint(st[m0 * PSTR + kr + 4]);
            uint32_t a3 = __float_as_uint(st[(m0 + 8) * PSTR + kr + 4]);
            #pragma unroll
            for (int nt = 0; nt < 8; nt++) {
                int n0 = chalf * 64 + nt * 8 + (lane >> 2);
                uint32_t b0 = __float_as_uint(vs[kr * VSTR + n0]);
                uint32_t b1 = __float_as_uint(vs[(kr + 4) * VSTR + n0]);
                mma_tf32(o[nt][0], o[nt][1], o[nt][2], o[nt][3], a0, a1, a2, a3, b0, b1);
            }
        }
        __syncthreads();
    }

    float inv0 = 1.f / lrow[mrow0];
    float inv1 = 1.f / lrow[mrow0 + 8];
    #pragma unroll
    for (int nt = 0; nt < 8; nt++) {
        int c = h * HD + chalf * 64 + nt * 8 + 2 * (lane & 3);
        size_t o0 = (size_t)(q0 + mrow0) * K2 + c;
        size_t o1 = (size_t)(q0 + mrow0 + 8) * K2 + c;
        *(float2*)&g_cat[o0] = make_float2(f2tf(o[nt][0] * inv0), f2tf(o[nt][1] * inv0));
        *(float2*)&g_cat[o1] = make_float2(f2tf(o[nt][2] * inv1), f2tf(o[nt][3] * inv1));
    }
}

// ---------------- launch ----------------
extern "C" void kernel_launch(void* const* d_in, const int* in_sizes, int n_in,
                              void* d_out, int out_size) {
    const float* hidden = (const float*)d_in[0];
    const float* temb   = (const float*)d_in[1];
    const float* cosb   = (const float*)d_in[2];
    const float* sinb   = (const float*)d_in[3];
    const float* ada_w  = (const float*)d_in[4];
    const float* ada_b  = (const float*)d_in[5];
    const float* lin1_w = (const float*)d_in[6];
    const float* lin1_b = (const float*)d_in[7];
    const float* lin2_w = (const float*)d_in[8];
    const float* lin2_b = (const float*)d_in[9];
    float* out = (float*)d_out;

    float *p_normx, *p_proj, *p_cat, *p_emb, *p_w1t, *p_w2t;
    cudaGetSymbolAddress((void**)&p_normx, g_normx);
    cudaGetSymbolAddress((void**)&p_proj,  g_proj);
    cudaGetSymbolAddress((void**)&p_cat,   g_cat);
    cudaGetSymbolAddress((void**)&p_emb,   g_emb);
    cudaGetSymbolAddress((void**)&p_w1t,   g_w1t);
    cudaGetSymbolAddress((void**)&p_w2t,   g_w2t);

    cudaFuncSetAttribute(attn_kernel,
                         cudaFuncAttributeMaxDynamicSharedMemorySize, (int)ATTN_SMEM);
    cudaFuncSetAttribute(tgemm_k<1>,
                         cudaFuncAttributeMaxDynamicSharedMemorySize, (int)GEMM_SMEM);
    cudaFuncSetAttribute(tgemm_k<2>,
                         cudaFuncAttributeMaxDynamicSharedMemorySize, (int)GEMM_SMEM);

    // pre-round weights to tf32
    {
        int n4a = (int)((size_t)HID * N1 / 4);
        int n4b = (int)((size_t)K2 * HID / 4);
        wround_kernel<<<(n4a + 255) / 256, 256>>>(lin1_w, p_w1t, n4a);
        wround_kernel<<<(n4b + 255) / 256, 256>>>(lin2_w, p_w2t, n4b);
    }

    silu_kernel<<<(HID + 255) / 256, 256>>>(temb);
    ada_kernel<<<(3 * HID + 255) / 256, 256>>>(ada_w, ada_b);
    ln_kernel<<<L_, 256>>>(hidden);

    tgemm_k<2><<<dim3(N1 / 128, L_ / 128), 256, GEMM_SMEM>>>(
        p_normx, p_w1t, lin1_b, nullptr, nullptr, p_proj, p_cat, L_, N1, HID);

    qkv_kernel<<<dim3(L_, HEADS), HD>>>(cosb, sinb,
                                        (const float*)d_in[10], (const float*)d_in[11]);
    attn_kernel<<<dim3(L_ / 64, HEADS), 256, ATTN_SMEM>>>();

    tgemm_k<1><<<dim3(HID / 128, L_ / 128), 256, GEMM_SMEM>>>(
        p_cat, p_w2t, lin2_b, hidden, p_emb + 2 * HID, out, nullptr, L_, HID, K2);
}

// round 6
// speedup vs baseline: 4.0042x; 1.0947x over previous
#include <cuda_runtime.h>
#include <math.h>
#include <stdint.h>

// ---------------- problem constants ----------------
#define HID   3072
#define HEADS 24
#define HD    128
#define MLP_  12288
#define L_    2304
#define TXT_  256
#define IMG   2048
#define N1    (3*HID + MLP_)      // 21504
#define K2    (HID + MLP_)        // 15360
#define QKV3  (3*HID)             // 9216
#define ADA_SPLITS 12

// ---------------- scratch ----------------
__device__ __align__(256) float g_silu[HID];
__device__ __align__(256) float g_emb[3*HID];
__device__ __align__(256) float g_adapart[ADA_SPLITS][3*HID];
__device__ __align__(256) float g_normx[(size_t)L_*HID];
__device__ __align__(256) float g_proj[(size_t)L_*QKV3];
__device__ __align__(256) float g_q[(size_t)HEADS*L_*HD];
__device__ __align__(256) float g_k[(size_t)HEADS*L_*HD];
__device__ __align__(256) float g_v[(size_t)HEADS*L_*HD];
__device__ __align__(256) float g_cat[(size_t)L_*K2];
__device__ __align__(256) float g_w1t[(size_t)HID*N1];
__device__ __align__(256) float g_w2t[(size_t)K2*HID];

// ---------------- tf32 / async helpers ----------------
__device__ __forceinline__ float f2tf(float x) {
    uint32_t u;
    asm("cvt.rna.tf32.f32 %0, %1;" : "=r"(u) : "f"(x));
    return __uint_as_float(u);
}
__device__ __forceinline__ void mma_tf32(float& c0, float& c1, float& c2, float& c3,
                                         uint32_t a0, uint32_t a1, uint32_t a2, uint32_t a3,
                                         uint32_t b0, uint32_t b1) {
    asm volatile("mma.sync.aligned.m16n8k8.row.col.f32.tf32.tf32.f32 "
                 "{%0,%1,%2,%3}, {%4,%5,%6,%7}, {%8,%9}, {%0,%1,%2,%3};"
                 : "+f"(c0), "+f"(c1), "+f"(c2), "+f"(c3)
                 : "r"(a0), "r"(a1), "r"(a2), "r"(a3), "r"(b0), "r"(b1));
}
__device__ __forceinline__ void cp16(float* dst, const float* src) {
    uint32_t d = (uint32_t)__cvta_generic_to_shared(dst);
    asm volatile("cp.async.cg.shared.global [%0], [%1], 16;\n" :: "r"(d), "l"(src));
}
__device__ __forceinline__ void ldmx4(uint32_t* r, const float* p) {
    uint32_t a = (uint32_t)__cvta_generic_to_shared(p);
    asm volatile("ldmatrix.sync.aligned.m8n8.x4.shared.b16 {%0,%1,%2,%3}, [%4];"
                 : "=r"(r[0]), "=r"(r[1]), "=r"(r[2]), "=r"(r[3]) : "r"(a));
}
#define CP_COMMIT() asm volatile("cp.async.commit_group;\n" ::: "memory")
#define CP_WAIT2()  asm volatile("cp.async.wait_group 2;\n" ::: "memory")

// ---------------- 0: weight rounding ----------------
__global__ void wround_kernel(const float* __restrict__ w, float* __restrict__ o, int n4) {
    int i = blockIdx.x * 256 + threadIdx.x;
    if (i < n4) {
        float4 v = ((const float4*)w)[i];
        float4 t = make_float4(f2tf(v.x), f2tf(v.y), f2tf(v.z), f2tf(v.w));
        ((float4*)o)[i] = t;
    }
}

// ---------------- 1: silu ----------------
__global__ void silu_kernel(const float* __restrict__ temb) {
    int i = blockIdx.x * 256 + threadIdx.x;
    if (i < HID) {
        float t = temb[i];
        g_silu[i] = t / (1.f + __expf(-t));
    }
}

// ---------------- 2a: adaLN GEMV split-K partials ----------------
__global__ void ada_split_kernel(const float* __restrict__ ada_w) {
    int j = blockIdx.x * 256 + threadIdx.x;       // 0..9215
    int ks = blockIdx.y;                          // k-slice
    int k0 = ks * (HID / ADA_SPLITS);             // 256 per slice
    float acc = 0.f;
    const float* wp = ada_w + (size_t)k0 * (3*HID) + j;
    #pragma unroll 8
    for (int i = 0; i < HID / ADA_SPLITS; i++)
        acc += g_silu[k0 + i] * wp[(size_t)i * (3*HID)];
    g_adapart[ks][j] = acc;
}

// ---------------- 2b: adaLN reduce + bias ----------------
__global__ void ada_reduce_kernel(const float* __restrict__ ada_b) {
    int j = blockIdx.x * 256 + threadIdx.x;
    if (j >= 3*HID) return;
    float acc = ada_b[j];
    #pragma unroll
    for (int s = 0; s < ADA_SPLITS; s++) acc += g_adapart[s][j];
    g_emb[j] = acc;
}

// ---------------- 3: layernorm + scale/shift (writes tf32-rounded) ----------------
__global__ void ln_kernel(const float* __restrict__ x) {
    int t = blockIdx.x;
    const float* row = x + (size_t)t * HID;
    float s = 0.f, s2 = 0.f;
    for (int i = threadIdx.x; i < HID; i += 256) {
        float v = row[i];
        s += v; s2 += v * v;
    }
    #pragma unroll
    for (int o = 16; o; o >>= 1) {
        s  += __shfl_xor_sync(~0u, s,  o);
        s2 += __shfl_xor_sync(~0u, s2, o);
    }
    __shared__ float rs[8], rs2[8], smu, srinv;
    int w = threadIdx.x >> 5, lane = threadIdx.x & 31;
    if (lane == 0) { rs[w] = s; rs2[w] = s2; }
    __syncthreads();
    if (threadIdx.x == 0) {
        float a = 0.f, b = 0.f;
        #pragma unroll
        for (int i = 0; i < 8; i++) { a += rs[i]; b += rs2[i]; }
        float mu = a / HID;
        float var = b / HID - mu * mu;
        smu = mu; srinv = rsqrtf(var + 1e-6f);
    }
    __syncthreads();
    float mu = smu, rinv = srinv;
    for (int i = threadIdx.x; i < HID; i += 256) {
        float sc = 1.f + g_emb[HID + i];
        float sh = g_emb[i];
        g_normx[(size_t)t * HID + i] = f2tf((row[i] - mu) * rinv * sc + sh);
    }
}

// ---------------- tf32 GEMM: 128x128x16 tiles, cp.async 4-stage, ldmatrix A ----
#define AST 20
#define BST 136
#define STAGES 4
#define A_STG (128*AST)
#define B_STG (16*BST)
#define GEMM_SMEM ((STAGES*(A_STG + B_STG)) * sizeof(float))

template<int MODE>
__global__ __launch_bounds__(256, 2) void tgemm_k(
    const float* __restrict__ A, const float* __restrict__ B,
    const float* __restrict__ bias, const float* __restrict__ resid,
    const float* __restrict__ gate,
    float* __restrict__ C, float* __restrict__ C2, int M, int N, int K)
{
    extern __shared__ float sm[];
    float* As = sm;
    float* Bs = sm + STAGES * A_STG;

    int tid = threadIdx.x;
    int wid = tid >> 5, lane = tid & 31;
    int wm = wid >> 2, wn = wid & 3;
    int bm = blockIdx.y, bn = blockIdx.x;

    const float* Ab = A + (size_t)bm * 128 * K;
    const float* Bb = B + (size_t)bn * 128;

    float acc[4][4][4];
    #pragma unroll
    for (int i = 0; i < 4; i++)
        #pragma unroll
        for (int j = 0; j < 4; j++)
            #pragma unroll
            for (int q = 0; q < 4; q++) acc[i][j][q] = 0.f;

    int nkt = K / 16;

    #define LOAD_TILE(stg, kt_) do {                                            \
        int kg = (kt_) * 16;                                                    \
        float* as_ = As + (stg) * A_STG;                                        \
        float* bs_ = Bs + (stg) * B_STG;                                        \
        _Pragma("unroll")                                                       \
        for (int i_ = 0; i_ < 2; i_++) {                                        \
            int id = tid + i_ * 256;                                            \
            int row = id >> 2, c = (id & 3) * 4;                                \
            cp16(as_ + row * AST + c, Ab + (size_t)row * K + kg + c);           \
        }                                                                       \
        _Pragma("unroll")                                                       \
        for (int i_ = 0; i_ < 2; i_++) {                                        \
            int id = tid + i_ * 256;                                            \
            int row = id >> 5, c = (id & 31) * 4;                               \
            cp16(bs_ + row * BST + c, Bb + (size_t)(kg + row) * N + c);         \
        }                                                                       \
    } while (0)

    #pragma unroll
    for (int s = 0; s < STAGES - 1; s++) {
        LOAD_TILE(s, s);
        CP_COMMIT();
    }

    int lrow = lane & 15;
    int lkc  = (lane >> 4) * 4;

    for (int kt = 0; kt < nkt; kt++) {
        CP_WAIT2();
        __syncthreads();
        int s = kt & (STAGES - 1);
        if (kt + STAGES - 1 < nkt) {
            LOAD_TILE((kt + STAGES - 1) & (STAGES - 1), kt + STAGES - 1);
        }
        CP_COMMIT();

        const float* as_ = As + s * A_STG;
        const float* bs_ = Bs + s * B_STG;

        #pragma unroll
        for (int ks = 0; ks < 2; ks++) {
            uint32_t af[4][4], bf[4][2];
            #pragma unroll
            for (int mt = 0; mt < 4; mt++) {
                int m = wm * 64 + mt * 16 + lrow;
                ldmx4(af[mt], as_ + m * AST + ks * 8 + lkc);
            }
            int kr = ks * 8 + (lane & 3);
            #pragma unroll
            for (int nt = 0; nt < 4; nt++) {
                int n0 = wn * 32 + nt * 8 + (lane >> 2);
                bf[nt][0] = __float_as_uint(bs_[kr * BST + n0]);
                bf[nt][1] = __float_as_uint(bs_[(kr + 4) * BST + n0]);
            }
            #pragma unroll
            for (int mt = 0; mt < 4; mt++)
                #pragma unroll
                for (int nt = 0; nt < 4; nt++)
                    mma_tf32(acc[mt][nt][0], acc[mt][nt][1], acc[mt][nt][2], acc[mt][nt][3],
                             af[mt][0], af[mt][1], af[mt][2], af[mt][3],
                             bf[nt][0], bf[nt][1]);
        }
    }
    #undef LOAD_TILE

    #pragma unroll
    for (int mt = 0; mt < 4; mt++) {
        int r0 = bm * 128 + wm * 64 + mt * 16 + (lane >> 2);
        #pragma unroll
        for (int nt = 0; nt < 4; nt++) {
            int c0 = bn * 128 + wn * 32 + nt * 8 + 2 * (lane & 3);
            float bia0 = bias[c0], bia1 = bias[c0 + 1];
            float t00 = acc[mt][nt][0] + bia0, t01 = acc[mt][nt][1] + bia1;
            float t10 = acc[mt][nt][2] + bia0, t11 = acc[mt][nt][3] + bia1;
            if (MODE == 1) {
                size_t o0 = (size_t)r0 * N + c0;
                size_t o1 = (size_t)(r0 + 8) * N + c0;
                float gg0 = gate[c0], gg1 = gate[c0 + 1];
                float2 r_0 = *(const float2*)(resid + o0);
                float2 r_1 = *(const float2*)(resid + o1);
                *(float2*)(C + o0) = make_float2(r_0.x + t00 * gg0, r_0.y + t01 * gg1);
                *(float2*)(C + o1) = make_float2(r_1.x + t10 * gg0, r_1.y + t11 * gg1);
            } else {
                if (c0 < QKV3) {
                    size_t o0 = (size_t)r0 * QKV3 + c0;
                    size_t o1 = (size_t)(r0 + 8) * QKV3 + c0;
                    *(float2*)(C + o0) = make_float2(t00, t01);
                    *(float2*)(C + o1) = make_float2(t10, t11);
                } else {
                    int cc = c0 - QKV3;
                    size_t o0 = (size_t)r0 * K2 + HID + cc;
                    size_t o1 = (size_t)(r0 + 8) * K2 + HID + cc;
                    const float kA = 0.7978845608028654f, kB = 0.044715f;
                    float g00 = 0.5f * t00 * (1.f + tanhf(kA * (t00 + kB * t00 * t00 * t00)));
                    float g01 = 0.5f * t01 * (1.f + tanhf(kA * (t01 + kB * t01 * t01 * t01)));
                    float g10 = 0.5f * t10 * (1.f + tanhf(kA * (t10 + kB * t10 * t10 * t10)));
                    float g11 = 0.5f * t11 * (1.f + tanhf(kA * (t11 + kB * t11 * t11 * t11)));
                    *(float2*)(C2 + o0) = make_float2(f2tf(g00), f2tf(g01));
                    *(float2*)(C2 + o1) = make_float2(f2tf(g10), f2tf(g11));
                }
            }
        }
    }
}

// ---------------- 5: qkv split + rmsnorm + rope ----------------
__global__ void qkv_kernel(const float* __restrict__ cosb, const float* __restrict__ sinb,
                           const float* __restrict__ qn,   const float* __restrict__ kn) {
    int t = blockIdx.x, h = blockIdx.y, d = threadIdx.x;
    const float* p = g_proj + (size_t)t * QKV3 + h * HD + d;
    float qv = p[0], kv = p[HID], vv = p[2*HID];

    float sq = qv * qv, sk = kv * kv;
    #pragma unroll
    for (int o = 16; o; o >>= 1) {
        sq += __shfl_xor_sync(~0u, sq, o);
        sk += __shfl_xor_sync(~0u, sk, o);
    }
    __shared__ float rq[4], rk[4];
    int w = d >> 5;
    if ((d & 31) == 0) { rq[w] = sq; rk[w] = sk; }
    __syncthreads();
    sq = rq[0] + rq[1] + rq[2] + rq[3];
    sk = rk[0] + rk[1] + rk[2] + rk[3];
    qv = qv * rsqrtf(sq / HD + 1e-6f) * qn[d];
    kv = kv * rsqrtf(sk / HD + 1e-6f) * kn[d];

    if (t < IMG) {
        float c = cosb[(size_t)t * HD + d];
        float s = sinb[(size_t)t * HD + d];
        float qo = __shfl_xor_sync(~0u, qv, 1);
        float ko = __shfl_xor_sync(~0u, kv, 1);
        float qr = (d & 1) ? qo : -qo;
        float kr = (d & 1) ? ko : -ko;
        qv = qv * c + qr * s;
        kv = kv * c + kr * s;
    }
    const float scale = 0.08838834764831845f;
    size_t o = ((size_t)h * L_ + t) * HD + d;
    g_q[o] = f2tf(qv * scale);
    g_k[o] = f2tf(kv);
    g_v[o] = f2tf(vv);
}

// ---------------- 7: flash attention, tf32 tensor cores ----------------
#define QSTR 132
#define VSTR 136
#define PSTR 68
#define OFF_QS 0
#define OFF_KS (64*QSTR)
#define OFF_VS (OFF_KS + 64*QSTR)
#define OFF_ST (OFF_VS + 64*VSTR)
#define OFF_MR (OFF_ST + 64*PSTR)
#define OFF_LR (OFF_MR + 64)
#define OFF_PM (OFF_LR + 64)
#define OFF_PS (OFF_PM + 128)
#define ATTN_F (OFF_PS + 128)
#define ATTN_SMEM (ATTN_F * sizeof(float))

__global__ __launch_bounds__(256) void attn_kernel() {
    extern __shared__ float smf[];
    float* qs = smf + OFF_QS;
    float* ks = smf + OFF_KS;
    float* vs = smf + OFF_VS;
    float* st = smf + OFF_ST;
    float* mrow = smf + OFF_MR;
    float* lrow = smf + OFF_LR;
    float* pm = smf + OFF_PM;
    float* ps = smf + OFF_PS;

    int h  = blockIdx.y;
    int q0 = blockIdx.x * 64;
    const float* Qp = g_q + ((size_t)h * L_ + q0) * HD;
    const float* Kp = g_k + (size_t)h * L_ * HD;
    const float* Vp = g_v + (size_t)h * L_ * HD;

    int tid = threadIdx.x;
    int wid = tid >> 5, lane = tid & 31;
    int mtile = wid & 3, chalf = wid >> 2;
    int mrow0 = mtile * 16 + (lane >> 2);

    for (int i = tid; i < 64 * 32; i += 256) {
        int r = i >> 5, c4 = (i & 31) * 4;
        *(float4*)&qs[r * QSTR + c4] = *(const float4*)(Qp + (size_t)r * HD + c4);
    }
    if (tid < 64) { mrow[tid] = -1e30f; lrow[tid] = 0.f; }

    float o[8][4];
    #pragma unroll
    for (int i = 0; i < 8; i++)
        #pragma unroll
        for (int j = 0; j < 4; j++) o[i][j] = 0.f;
    __syncthreads();

    for (int k0 = 0; k0 < L_; k0 += 64) {
        for (int i = tid; i < 64 * 32; i += 256) {
            int r = i >> 5, c4 = (i & 31) * 4;
            *(float4*)&ks[r * QSTR + c4] = *(const float4*)(Kp + (size_t)(k0 + r) * HD + c4);
            *(float4*)&vs[r * VSTR + c4] = *(const float4*)(Vp + (size_t)(k0 + r) * HD + c4);
        }
        __syncthreads();

        float s[4][4];
        #pragma unroll
        for (int nt = 0; nt < 4; nt++)
            #pragma unroll
            for (int j = 0; j < 4; j++) s[nt][j] = 0.f;

        #pragma unroll
        for (int kk = 0; kk < 16; kk++) {
            int kr = kk * 8 + (lane & 3);
            int m0 = mtile * 16 + (lane >> 2);
            uint32_t a0 = __float_as_uint(qs[m0 * QSTR + kr]);
            uint32_t a1 = __float_as_uint(qs[(m0 + 8) * QSTR + kr]);
            uint32_t a2 = __float_as_uint(qs[m0 * QSTR + kr + 4]);
            uint32_t a3 = __float_as_uint(qs[(m0 + 8) * QSTR + kr + 4]);
            #pragma unroll
            for (int nt = 0; nt < 4; nt++) {
                int n0 = chalf * 32 + nt * 8 + (lane >> 2);
                uint32_t b0 = __float_as_uint(ks[n0 * QSTR + kr]);
                uint32_t b1 = __float_as_uint(ks[n0 * QSTR + kr + 4]);
                mma_tf32(s[nt][0], s[nt][1], s[nt][2], s[nt][3], a0, a1, a2, a3, b0, b1);
            }
        }

        float rmax0 = -1e30f, rmax1 = -1e30f;
        #pragma unroll
        for (int nt = 0; nt < 4; nt++) {
            rmax0 = fmaxf(rmax0, fmaxf(s[nt][0], s[nt][1]));
            rmax1 = fmaxf(rmax1, fmaxf(s[nt][2], s[nt][3]));
        }
        #pragma unroll
        for (int off = 1; off <= 2; off <<= 1) {
            rmax0 = fmaxf(rmax0, __shfl_xor_sync(~0u, rmax0, off));
            rmax1 = fmaxf(rmax1, __shfl_xor_sync(~0u, rmax1, off));
        }
        if ((lane & 3) == 0) {
            pm[chalf * 64 + mrow0] = rmax0;
            pm[chalf * 64 + mrow0 + 8] = rmax1;
        }
        __syncthreads();

        float mo0 = mrow[mrow0], mo1 = mrow[mrow0 + 8];
        float mn0 = fmaxf(mo0, fmaxf(pm[mrow0], pm[64 + mrow0]));
        float mn1 = fmaxf(mo1, fmaxf(pm[mrow0 + 8], pm[64 + mrow0 + 8]));
        float al0 = __expf(mo0 - mn0), al1 = __expf(mo1 - mn1);

        float rs0 = 0.f, rs1 = 0.f;
        #pragma unroll
        for (int nt = 0; nt < 4; nt++) {
            float p0 = __expf(s[nt][0] - mn0);
            float p1 = __expf(s[nt][1] - mn0);
            float p2 = __expf(s[nt][2] - mn1);
            float p3 = __expf(s[nt][3] - mn1);
            rs0 += p0 + p1; rs1 += p2 + p3;
            int c = chalf * 32 + nt * 8 + 2 * (lane & 3);
            *(float2*)&st[mrow0 * PSTR + c] = make_float2(f2tf(p0), f2tf(p1));
            *(float2*)&st[(mrow0 + 8) * PSTR + c] = make_float2(f2tf(p2), f2tf(p3));
        }
        #pragma unroll
        for (int off = 1; off <= 2; off <<= 1) {
            rs0 += __shfl_xor_sync(~0u, rs0, off);
            rs1 += __shfl_xor_sync(~0u, rs1, off);
        }
        if ((lane & 3) == 0) {
            ps[chalf * 64 + mrow0] = rs0;
            ps[chalf * 64 + mrow0 + 8] = rs1;
        }
        #pragma unroll
        for (int nt = 0; nt < 8; nt++) {
            o[nt][0] *= al0; o[nt][1] *= al0;
            o[nt][2] *= al1; o[nt][3] *= al1;
        }
        __syncthreads();

        if (tid < 64) {
            float mo = mrow[tid];
            float mn = fmaxf(mo, fmaxf(pm[tid], pm[64 + tid]));
            lrow[tid] = lrow[tid] * __expf(mo - mn) + ps[tid] + ps[64 + tid];
            mrow[tid] = mn;
        }

        #pragma unroll
        for (int kk = 0; kk < 8; kk++) {
            int kr = kk * 8 + (lane & 3);
            int m0 = mtile * 16 + (lane >> 2);
            uint32_t a0 = __float_as_uint(st[m0 * PSTR + kr]);
            uint32_t a1 = __float_as_uint(st[(m0 + 8) * PSTR + kr]);
            uint32_t a2 = __float_as_uint(st[m0 * PSTR + kr + 4]);
            uint32_t a3 = __float_as_uint(st[(m0 + 8) * PSTR + kr + 4]);
            #pragma unroll
            for (int nt = 0; nt < 8; nt++) {
                int n0 = chalf * 64 + nt * 8 + (lane >> 2);
                uint32_t b0 = __float_as_uint(vs[kr * VSTR + n0]);
                uint32_t b1 = __float_as_uint(vs[(kr + 4) * VSTR + n0]);
                mma_tf32(o[nt][0], o[nt][1], o[nt][2], o[nt][3], a0, a1, a2, a3, b0, b1);
            }
        }
        __syncthreads();
    }

    float inv0 = 1.f / lrow[mrow0];
    float inv1 = 1.f / lrow[mrow0 + 8];
    #pragma unroll
    for (int nt = 0; nt < 8; nt++) {
        int c = h * HD + chalf * 64 + nt * 8 + 2 * (lane & 3);
        size_t o0 = (size_t)(q0 + mrow0) * K2 + c;
        size_t o1 = (size_t)(q0 + mrow0 + 8) * K2 + c;
        *(float2*)&g_cat[o0] = make_float2(f2tf(o[nt][0] * inv0), f2tf(o[nt][1] * inv0));
        *(float2*)&g_cat[o1] = make_float2(f2tf(o[nt][2] * inv1), f2tf(o[nt][3] * inv1));
    }
}

// ---------------- launch ----------------
extern "C" void kernel_launch(void* const* d_in, const int* in_sizes, int n_in,
                              void* d_out, int out_size) {
    const float* hidden = (const float*)d_in[0];
    const float* temb   = (const float*)d_in[1];
    const float* cosb   = (const float*)d_in[2];
    const float* sinb   = (const float*)d_in[3];
    const float* ada_w  = (const float*)d_in[4];
    const float* ada_b  = (const float*)d_in[5];
    const float* lin1_w = (const float*)d_in[6];
    const float* lin1_b = (const float*)d_in[7];
    const float* lin2_w = (const float*)d_in[8];
    const float* lin2_b = (const float*)d_in[9];
    float* out = (float*)d_out;

    float *p_normx, *p_proj, *p_cat, *p_emb, *p_w1t, *p_w2t;
    cudaGetSymbolAddress((void**)&p_normx, g_normx);
    cudaGetSymbolAddress((void**)&p_proj,  g_proj);
    cudaGetSymbolAddress((void**)&p_cat,   g_cat);
    cudaGetSymbolAddress((void**)&p_emb,   g_emb);
    cudaGetSymbolAddress((void**)&p_w1t,   g_w1t);
    cudaGetSymbolAddress((void**)&p_w2t,   g_w2t);

    cudaFuncSetAttribute(attn_kernel,
                         cudaFuncAttributeMaxDynamicSharedMemorySize, (int)ATTN_SMEM);
    cudaFuncSetAttribute(tgemm_k<1>,
                         cudaFuncAttributeMaxDynamicSharedMemorySize, (int)GEMM_SMEM);
    cudaFuncSetAttribute(tgemm_k<2>,
                         cudaFuncAttributeMaxDynamicSharedMemorySize, (int)GEMM_SMEM);

    {
        int n4a = (int)((size_t)HID * N1 / 4);
        int n4b = (int)((size_t)K2 * HID / 4);
        wround_kernel<<<(n4a + 255) / 256, 256>>>(lin1_w, p_w1t, n4a);
        wround_kernel<<<(n4b + 255) / 256, 256>>>(lin2_w, p_w2t, n4b);
    }

    silu_kernel<<<(HID + 255) / 256, 256>>>(temb);
    ada_split_kernel<<<dim3(3 * HID / 256, ADA_SPLITS), 256>>>(ada_w);
    ada_reduce_kernel<<<(3 * HID + 255) / 256, 256>>>(ada_b);
    ln_kernel<<<L_, 256>>>(hidden);

    tgemm_k<2><<<dim3(N1 / 128, L_ / 128), 256, GEMM_SMEM>>>(
        p_normx, p_w1t, lin1_b, nullptr, nullptr, p_proj, p_cat, L_, N1, HID);

    qkv_kernel<<<dim3(L_, HEADS), HD>>>(cosb, sinb,
                                        (const float*)d_in[10], (const float*)d_in[11]);
    attn_kernel<<<dim3(L_ / 64, HEADS), 256, ATTN_SMEM>>>();

    tgemm_k<1><<<dim3(HID / 128, L_ / 128), 256, GEMM_SMEM>>>(
        p_cat, p_w2t, lin2_b, hidden, p_emb + 2 * HID, out, nullptr, L_, HID, K2);
}

// round 7
// speedup vs baseline: 4.3773x; 1.0932x over previous
#include <cuda_runtime.h>
#include <math.h>
#include <stdint.h>

// ---------------- problem constants ----------------
#define HID   3072
#define HEADS 24
#define HD    128
#define MLP_  12288
#define L_    2304
#define TXT_  256
#define IMG   2048
#define N1    (3*HID + MLP_)      // 21504
#define K2    (HID + MLP_)        // 15360
#define QKV3  (3*HID)             // 9216
#define ADA_SPLITS 12

// ---------------- scratch ----------------
__device__ __align__(256) float g_silu[HID];
__device__ __align__(256) float g_emb[3*HID];
__device__ __align__(256) float g_adapart[ADA_SPLITS][3*HID];
__device__ __align__(256) float g_normx[(size_t)L_*HID];
__device__ __align__(256) float g_proj[(size_t)L_*QKV3];
__device__ __align__(256) float g_q[(size_t)HEADS*L_*HD];
__device__ __align__(256) float g_k[(size_t)HEADS*L_*HD];
__device__ __align__(256) float g_v[(size_t)HEADS*L_*HD];
__device__ __align__(256) float g_cat[(size_t)L_*K2];
__device__ __align__(256) float g_w1t[(size_t)HID*N1];
__device__ __align__(256) float g_w2t[(size_t)K2*HID];

// ---------------- tf32 / async helpers ----------------
__device__ __forceinline__ float f2tf(float x) {
    uint32_t u;
    asm("cvt.rna.tf32.f32 %0, %1;" : "=r"(u) : "f"(x));
    return __uint_as_float(u);
}
__device__ __forceinline__ void mma_tf32(float& c0, float& c1, float& c2, float& c3,
                                         uint32_t a0, uint32_t a1, uint32_t a2, uint32_t a3,
                                         uint32_t b0, uint32_t b1) {
    asm volatile("mma.sync.aligned.m16n8k8.row.col.f32.tf32.tf32.f32 "
                 "{%0,%1,%2,%3}, {%4,%5,%6,%7}, {%8,%9}, {%0,%1,%2,%3};"
                 : "+f"(c0), "+f"(c1), "+f"(c2), "+f"(c3)
                 : "r"(a0), "r"(a1), "r"(a2), "r"(a3), "r"(b0), "r"(b1));
}
__device__ __forceinline__ void cp16(float* dst, const float* src) {
    uint32_t d = (uint32_t)__cvta_generic_to_shared(dst);
    asm volatile("cp.async.cg.shared.global [%0], [%1], 16;\n" :: "r"(d), "l"(src));
}
__device__ __forceinline__ void ldmx4(uint32_t* r, const float* p) {
    uint32_t a = (uint32_t)__cvta_generic_to_shared(p);
    asm volatile("ldmatrix.sync.aligned.m8n8.x4.shared.b16 {%0,%1,%2,%3}, [%4];"
                 : "=r"(r[0]), "=r"(r[1]), "=r"(r[2]), "=r"(r[3]) : "r"(a));
}
#define CP_COMMIT() asm volatile("cp.async.commit_group;\n" ::: "memory")
#define CP_WAIT2()  asm volatile("cp.async.wait_group 2;\n" ::: "memory")

// ---------------- 0: weight rounding ----------------
__global__ void wround_kernel(const float* __restrict__ w, float* __restrict__ o, int n4) {
    int i = blockIdx.x * 256 + threadIdx.x;
    if (i < n4) {
        float4 v = ((const float4*)w)[i];
        float4 t = make_float4(f2tf(v.x), f2tf(v.y), f2tf(v.z), f2tf(v.w));
        ((float4*)o)[i] = t;
    }
}

// ---------------- 1: silu ----------------
__global__ void silu_kernel(const float* __restrict__ temb) {
    int i = blockIdx.x * 256 + threadIdx.x;
    if (i < HID) {
        float t = temb[i];
        g_silu[i] = t / (1.f + __expf(-t));
    }
}

// ---------------- 2a: adaLN GEMV split-K partials ----------------
__global__ void ada_split_kernel(const float* __restrict__ ada_w) {
    int j = blockIdx.x * 256 + threadIdx.x;
    int ks = blockIdx.y;
    int k0 = ks * (HID / ADA_SPLITS);
    float acc = 0.f;
    const float* wp = ada_w + (size_t)k0 * (3*HID) + j;
    #pragma unroll 8
    for (int i = 0; i < HID / ADA_SPLITS; i++)
        acc += g_silu[k0 + i] * wp[(size_t)i * (3*HID)];
    g_adapart[ks][j] = acc;
}

// ---------------- 2b: adaLN reduce + bias ----------------
__global__ void ada_reduce_kernel(const float* __restrict__ ada_b) {
    int j = blockIdx.x * 256 + threadIdx.x;
    if (j >= 3*HID) return;
    float acc = ada_b[j];
    #pragma unroll
    for (int s = 0; s < ADA_SPLITS; s++) acc += g_adapart[s][j];
    g_emb[j] = acc;
}

// ---------------- 3: layernorm + scale/shift (writes tf32-rounded) ----------------
__global__ void ln_kernel(const float* __restrict__ x) {
    int t = blockIdx.x;
    const float* row = x + (size_t)t * HID;
    float s = 0.f, s2 = 0.f;
    for (int i = threadIdx.x; i < HID; i += 256) {
        float v = row[i];
        s += v; s2 += v * v;
    }
    #pragma unroll
    for (int o = 16; o; o >>= 1) {
        s  += __shfl_xor_sync(~0u, s,  o);
        s2 += __shfl_xor_sync(~0u, s2, o);
    }
    __shared__ float rs[8], rs2[8], smu, srinv;
    int w = threadIdx.x >> 5, lane = threadIdx.x & 31;
    if (lane == 0) { rs[w] = s; rs2[w] = s2; }
    __syncthreads();
    if (threadIdx.x == 0) {
        float a = 0.f, b = 0.f;
        #pragma unroll
        for (int i = 0; i < 8; i++) { a += rs[i]; b += rs2[i]; }
        float mu = a / HID;
        float var = b / HID - mu * mu;
        smu = mu; srinv = rsqrtf(var + 1e-6f);
    }
    __syncthreads();
    float mu = smu, rinv = srinv;
    for (int i = threadIdx.x; i < HID; i += 256) {
        float sc = 1.f + g_emb[HID + i];
        float sh = g_emb[i];
        g_normx[(size_t)t * HID + i] = f2tf((row[i] - mu) * rinv * sc + sh);
    }
}

// ---------------- tf32 GEMM: 128x128x16 tiles, cp.async 4-stage, ldmatrix A ----
#define AST 20
#define BST 136
#define STAGES 4
#define A_STG (128*AST)
#define B_STG (16*BST)
#define GEMM_SMEM ((STAGES*(A_STG + B_STG)) * sizeof(float))

template<int MODE>
__global__ __launch_bounds__(256, 2) void tgemm_k(
    const float* __restrict__ A, const float* __restrict__ B,
    const float* __restrict__ bias, const float* __restrict__ resid,
    const float* __restrict__ gate,
    float* __restrict__ C, float* __restrict__ C2, int M, int N, int K)
{
    extern __shared__ float sm[];
    float* As = sm;
    float* Bs = sm + STAGES * A_STG;

    int tid = threadIdx.x;
    int wid = tid >> 5, lane = tid & 31;
    int wm = wid >> 2, wn = wid & 3;
    int bm = blockIdx.y, bn = blockIdx.x;

    const float* Ab = A + (size_t)bm * 128 * K;
    const float* Bb = B + (size_t)bn * 128;

    float acc[4][4][4];
    #pragma unroll
    for (int i = 0; i < 4; i++)
        #pragma unroll
        for (int j = 0; j < 4; j++)
            #pragma unroll
            for (int q = 0; q < 4; q++) acc[i][j][q] = 0.f;

    int nkt = K / 16;

    #define LOAD_TILE(stg, kt_) do {                                            \
        int kg = (kt_) * 16;                                                    \
        float* as_ = As + (stg) * A_STG;                                        \
        float* bs_ = Bs + (stg) * B_STG;                                        \
        _Pragma("unroll")                                                       \
        for (int i_ = 0; i_ < 2; i_++) {                                        \
            int id = tid + i_ * 256;                                            \
            int row = id >> 2, c = (id & 3) * 4;                                \
            cp16(as_ + row * AST + c, Ab + (size_t)row * K + kg + c);           \
        }                                                                       \
        _Pragma("unroll")                                                       \
        for (int i_ = 0; i_ < 2; i_++) {                                        \
            int id = tid + i_ * 256;                                            \
            int row = id >> 5, c = (id & 31) * 4;                               \
            cp16(bs_ + row * BST + c, Bb + (size_t)(kg + row) * N + c);         \
        }                                                                       \
    } while (0)

    #pragma unroll
    for (int s = 0; s < STAGES - 1; s++) {
        LOAD_TILE(s, s);
        CP_COMMIT();
    }

    int lrow = lane & 15;
    int lkc  = (lane >> 4) * 4;

    for (int kt = 0; kt < nkt; kt++) {
        CP_WAIT2();
        __syncthreads();
        int s = kt & (STAGES - 1);
        if (kt + STAGES - 1 < nkt) {
            LOAD_TILE((kt + STAGES - 1) & (STAGES - 1), kt + STAGES - 1);
        }
        CP_COMMIT();

        const float* as_ = As + s * A_STG;
        const float* bs_ = Bs + s * B_STG;

        #pragma unroll
        for (int ks = 0; ks < 2; ks++) {
            uint32_t af[4][4], bf[4][2];
            #pragma unroll
            for (int mt = 0; mt < 4; mt++) {
                int m = wm * 64 + mt * 16 + lrow;
                ldmx4(af[mt], as_ + m * AST + ks * 8 + lkc);
            }
            int kr = ks * 8 + (lane & 3);
            #pragma unroll
            for (int nt = 0; nt < 4; nt++) {
                int n0 = wn * 32 + nt * 8 + (lane >> 2);
                bf[nt][0] = __float_as_uint(bs_[kr * BST + n0]);
                bf[nt][1] = __float_as_uint(bs_[(kr + 4) * BST + n0]);
            }
            #pragma unroll
            for (int mt = 0; mt < 4; mt++)
                #pragma unroll
                for (int nt = 0; nt < 4; nt++)
                    mma_tf32(acc[mt][nt][0], acc[mt][nt][1], acc[mt][nt][2], acc[mt][nt][3],
                             af[mt][0], af[mt][1], af[mt][2], af[mt][3],
                             bf[nt][0], bf[nt][1]);
        }
    }
    #undef LOAD_TILE

    #pragma unroll
    for (int mt = 0; mt < 4; mt++) {
        int r0 = bm * 128 + wm * 64 + mt * 16 + (lane >> 2);
        #pragma unroll
        for (int nt = 0; nt < 4; nt++) {
            int c0 = bn * 128 + wn * 32 + nt * 8 + 2 * (lane & 3);
            float bia0 = bias[c0], bia1 = bias[c0 + 1];
            float t00 = acc[mt][nt][0] + bia0, t01 = acc[mt][nt][1] + bia1;
            float t10 = acc[mt][nt][2] + bia0, t11 = acc[mt][nt][3] + bia1;
            if (MODE == 1) {
                size_t o0 = (size_t)r0 * N + c0;
                size_t o1 = (size_t)(r0 + 8) * N + c0;
                float gg0 = gate[c0], gg1 = gate[c0 + 1];
                float2 r_0 = *(const float2*)(resid + o0);
                float2 r_1 = *(const float2*)(resid + o1);
                *(float2*)(C + o0) = make_float2(r_0.x + t00 * gg0, r_0.y + t01 * gg1);
                *(float2*)(C + o1) = make_float2(r_1.x + t10 * gg0, r_1.y + t11 * gg1);
            } else {
                if (c0 < QKV3) {
                    size_t o0 = (size_t)r0 * QKV3 + c0;
                    size_t o1 = (size_t)(r0 + 8) * QKV3 + c0;
                    *(float2*)(C + o0) = make_float2(t00, t01);
                    *(float2*)(C + o1) = make_float2(t10, t11);
                } else {
                    int cc = c0 - QKV3;
                    size_t o0 = (size_t)r0 * K2 + HID + cc;
                    size_t o1 = (size_t)(r0 + 8) * K2 + HID + cc;
                    const float kA = 0.7978845608028654f, kB = 0.044715f;
                    float g00 = 0.5f * t00 * (1.f + tanhf(kA * (t00 + kB * t00 * t00 * t00)));
                    float g01 = 0.5f * t01 * (1.f + tanhf(kA * (t01 + kB * t01 * t01 * t01)));
                    float g10 = 0.5f * t10 * (1.f + tanhf(kA * (t10 + kB * t10 * t10 * t10)));
                    float g11 = 0.5f * t11 * (1.f + tanhf(kA * (t11 + kB * t11 * t11 * t11)));
                    *(float2*)(C2 + o0) = make_float2(f2tf(g00), f2tf(g01));
                    *(float2*)(C2 + o1) = make_float2(f2tf(g10), f2tf(g11));
                }
            }
        }
    }
}

// ---------------- 5: qkv split + rmsnorm + rope ----------------
__global__ void qkv_kernel(const float* __restrict__ cosb, const float* __restrict__ sinb,
                           const float* __restrict__ qn,   const float* __restrict__ kn) {
    int t = blockIdx.x, h = blockIdx.y, d = threadIdx.x;
    const float* p = g_proj + (size_t)t * QKV3 + h * HD + d;
    float qv = p[0], kv = p[HID], vv = p[2*HID];

    float sq = qv * qv, sk = kv * kv;
    #pragma unroll
    for (int o = 16; o; o >>= 1) {
        sq += __shfl_xor_sync(~0u, sq, o);
        sk += __shfl_xor_sync(~0u, sk, o);
    }
    __shared__ float rq[4], rk[4];
    int w = d >> 5;
    if ((d & 31) == 0) { rq[w] = sq; rk[w] = sk; }
    __syncthreads();
    sq = rq[0] + rq[1] + rq[2] + rq[3];
    sk = rk[0] + rk[1] + rk[2] + rk[3];
    qv = qv * rsqrtf(sq / HD + 1e-6f) * qn[d];
    kv = kv * rsqrtf(sk / HD + 1e-6f) * kn[d];

    if (t < IMG) {
        float c = cosb[(size_t)t * HD + d];
        float s = sinb[(size_t)t * HD + d];
        float qo = __shfl_xor_sync(~0u, qv, 1);
        float ko = __shfl_xor_sync(~0u, kv, 1);
        float qr = (d & 1) ? qo : -qo;
        float kr = (d & 1) ? ko : -ko;
        qv = qv * c + qr * s;
        kv = kv * c + kr * s;
    }
    const float scale = 0.08838834764831845f;
    size_t o = ((size_t)h * L_ + t) * HD + d;
    g_q[o] = f2tf(qv * scale);
    g_k[o] = f2tf(kv);
    g_v[o] = f2tf(vv);
}

// ---------------- 7: flash attention, BQ=128, register-resident Q ----------------
// 256 threads / 8 warps; warp w owns q rows [w*16, w*16+16) end-to-end.
// Q frags in regs; smem: [q-stage | P] reuse region + K + V chunk buffers.
#define QSTR 132
#define VSTR 136
#define PSTR 68
#define OFF_QP 0                     // q stage (128*132) then P (128*68)
#define OFF_KS (128*QSTR)
#define OFF_VS (OFF_KS + 64*QSTR)
#define ATTN_F (OFF_VS + 64*VSTR)
#define ATTN_SMEM (ATTN_F * sizeof(float))

__global__ __launch_bounds__(256) void attn_kernel() {
    extern __shared__ float smf[];
    float* qst = smf + OFF_QP;   // q stage, later P
    float* ks  = smf + OFF_KS;
    float* vs  = smf + OFF_VS;

    int h  = blockIdx.y;
    int q0 = blockIdx.x * 128;
    const float* Qp = g_q + ((size_t)h * L_ + q0) * HD;
    const float* Kp = g_k + (size_t)h * L_ * HD;
    const float* Vp = g_v + (size_t)h * L_ * HD;

    int tid = threadIdx.x;
    int wid = tid >> 5, lane = tid & 31;
    int r0 = wid * 16 + (lane >> 2);     // this thread's q rows: r0 and r0+8 (block-local)
    int lq = lane & 3;

    // stage Q (pre-scaled tf32 in g_q) into smem, coalesced
    for (int i = tid; i < 128 * 32; i += 256) {
        int r = i >> 5, c4 = (i & 31) * 4;
        *(float4*)&qst[r * QSTR + c4] = *(const float4*)(Qp + (size_t)r * HD + c4);
    }
    __syncthreads();

    // extract Q fragments to registers (conflict-free: bank = 4q + r)
    uint32_t qf[16][4];
    #pragma unroll
    for (int kk = 0; kk < 16; kk++) {
        int kr = kk * 8 + lq;
        qf[kk][0] = __float_as_uint(qst[r0 * QSTR + kr]);
        qf[kk][1] = __float_as_uint(qst[(r0 + 8) * QSTR + kr]);
        qf[kk][2] = __float_as_uint(qst[r0 * QSTR + kr + 4]);
        qf[kk][3] = __float_as_uint(qst[(r0 + 8) * QSTR + kr + 4]);
    }
    __syncthreads();   // qst now reusable as P

    float m0 = -1e30f, m1 = -1e30f, l0 = 0.f, l1 = 0.f;
    float o[16][4];
    #pragma unroll
    for (int i = 0; i < 16; i++)
        #pragma unroll
        for (int j = 0; j < 4; j++) o[i][j] = 0.f;

    for (int k0 = 0; k0 < L_; k0 += 64) {
        // load K/V chunk
        for (int i = tid; i < 64 * 32; i += 256) {
            int r = i >> 5, c4 = (i & 31) * 4;
            *(float4*)&ks[r * QSTR + c4] = *(const float4*)(Kp + (size_t)(k0 + r) * HD + c4);
            *(float4*)&vs[r * VSTR + c4] = *(const float4*)(Vp + (size_t)(k0 + r) * HD + c4);
        }
        __syncthreads();

        // S = Q @ K^T : 16 q-rows x 64 k-cols per warp
        float s[8][4];
        #pragma unroll
        for (int nt = 0; nt < 8; nt++)
            #pragma unroll
            for (int j = 0; j < 4; j++) s[nt][j] = 0.f;

        #pragma unroll
        for (int kk = 0; kk < 16; kk++) {
            int kr = kk * 8 + lq;
            #pragma unroll
            for (int nt = 0; nt < 8; nt++) {
                int n0 = nt * 8 + (lane >> 2);
                uint32_t b0 = __float_as_uint(ks[n0 * QSTR + kr]);
                uint32_t b1 = __float_as_uint(ks[n0 * QSTR + kr + 4]);
                mma_tf32(s[nt][0], s[nt][1], s[nt][2], s[nt][3],
                         qf[kk][0], qf[kk][1], qf[kk][2], qf[kk][3], b0, b1);
            }
        }

        // in-warp online softmax (rows r0 and r0+8, all 64 cols in this warp)
        float rmax0 = -1e30f, rmax1 = -1e30f;
        #pragma unroll
        for (int nt = 0; nt < 8; nt++) {
            rmax0 = fmaxf(rmax0, fmaxf(s[nt][0], s[nt][1]));
            rmax1 = fmaxf(rmax1, fmaxf(s[nt][2], s[nt][3]));
        }
        #pragma unroll
        for (int off = 1; off <= 2; off <<= 1) {
            rmax0 = fmaxf(rmax0, __shfl_xor_sync(~0u, rmax0, off));
            rmax1 = fmaxf(rmax1, __shfl_xor_sync(~0u, rmax1, off));
        }
        float mn0 = fmaxf(m0, rmax0), mn1 = fmaxf(m1, rmax1);
        float al0 = __expf(m0 - mn0), al1 = __expf(m1 - mn1);

        float rs0 = 0.f, rs1 = 0.f;
        #pragma unroll
        for (int nt = 0; nt < 8; nt++) {
            float p0 = __expf(s[nt][0] - mn0);
            float p1 = __expf(s[nt][1] - mn0);
            float p2 = __expf(s[nt][2] - mn1);
            float p3 = __expf(s[nt][3] - mn1);
            rs0 += p0 + p1; rs1 += p2 + p3;
            int c = nt * 8 + 2 * lq;
            *(float2*)&qst[r0 * PSTR + c] = make_float2(f2tf(p0), f2tf(p1));
            *(float2*)&qst[(r0 + 8) * PSTR + c] = make_float2(f2tf(p2), f2tf(p3));
        }
        #pragma unroll
        for (int off = 1; off <= 2; off <<= 1) {
            rs0 += __shfl_xor_sync(~0u, rs0, off);
            rs1 += __shfl_xor_sync(~0u, rs1, off);
        }
        l0 = l0 * al0 + rs0;  m0 = mn0;
        l1 = l1 * al1 + rs1;  m1 = mn1;

        #pragma unroll
        for (int nt = 0; nt < 16; nt++) {
            o[nt][0] *= al0; o[nt][1] *= al0;
            o[nt][2] *= al1; o[nt][3] *= al1;
        }
        __syncwarp();

        // O += P @ V : 16 rows x 128 hd-cols per warp
        #pragma unroll
        for (int kk = 0; kk < 8; kk++) {
            int kr = kk * 8 + lq;
            uint32_t a0 = __float_as_uint(qst[r0 * PSTR + kr]);
            uint32_t a1 = __float_as_uint(qst[(r0 + 8) * PSTR + kr]);
            uint32_t a2 = __float_as_uint(qst[r0 * PSTR + kr + 4]);
            uint32_t a3 = __float_as_uint(qst[(r0 + 8) * PSTR + kr + 4]);
            #pragma unroll
            for (int nt = 0; nt < 16; nt++) {
                int n0 = nt * 8 + (lane >> 2);
                uint32_t b0 = __float_as_uint(vs[kr * VSTR + n0]);
                uint32_t b1 = __float_as_uint(vs[(kr + 4) * VSTR + n0]);
                mma_tf32(o[nt][0], o[nt][1], o[nt][2], o[nt][3], a0, a1, a2, a3, b0, b1);
            }
        }
        __syncthreads();
    }

    float inv0 = 1.f / l0, inv1 = 1.f / l1;
    #pragma unroll
    for (int nt = 0; nt < 16; nt++) {
        int c = h * HD + nt * 8 + 2 * lq;
        size_t o0 = (size_t)(q0 + r0) * K2 + c;
        size_t o1 = (size_t)(q0 + r0 + 8) * K2 + c;
        *(float2*)&g_cat[o0] = make_float2(f2tf(o[nt][0] * inv0), f2tf(o[nt][1] * inv0));
        *(float2*)&g_cat[o1] = make_float2(f2tf(o[nt][2] * inv1), f2tf(o[nt][3] * inv1));
    }
}

// ---------------- launch ----------------
extern "C" void kernel_launch(void* const* d_in, const int* in_sizes, int n_in,
                              void* d_out, int out_size) {
    const float* hidden = (const float*)d_in[0];
    const float* temb   = (const float*)d_in[1];
    const float* cosb   = (const float*)d_in[2];
    const float* sinb   = (const float*)d_in[3];
    const float* ada_w  = (const float*)d_in[4];
    const float* ada_b  = (const float*)d_in[5];
    const float* lin1_w = (const float*)d_in[6];
    const float* lin1_b = (const float*)d_in[7];
    const float* lin2_w = (const float*)d_in[8];
    const float* lin2_b = (const float*)d_in[9];
    float* out = (float*)d_out;

    float *p_normx, *p_proj, *p_cat, *p_emb, *p_w1t, *p_w2t;
    cudaGetSymbolAddress((void**)&p_normx, g_normx);
    cudaGetSymbolAddress((void**)&p_proj,  g_proj);
    cudaGetSymbolAddress((void**)&p_cat,   g_cat);
    cudaGetSymbolAddress((void**)&p_emb,   g_emb);
    cudaGetSymbolAddress((void**)&p_w1t,   g_w1t);
    cudaGetSymbolAddress((void**)&p_w2t,   g_w2t);

    cudaFuncSetAttribute(attn_kernel,
                         cudaFuncAttributeMaxDynamicSharedMemorySize, (int)ATTN_SMEM);
    cudaFuncSetAttribute(tgemm_k<1>,
                         cudaFuncAttributeMaxDynamicSharedMemorySize, (int)GEMM_SMEM);
    cudaFuncSetAttribute(tgemm_k<2>,
                         cudaFuncAttributeMaxDynamicSharedMemorySize, (int)GEMM_SMEM);

    {
        int n4a = (int)((size_t)HID * N1 / 4);
        int n4b = (int)((size_t)K2 * HID / 4);
        wround_kernel<<<(n4a + 255) / 256, 256>>>(lin1_w, p_w1t, n4a);
        wround_kernel<<<(n4b + 255) / 256, 256>>>(lin2_w, p_w2t, n4b);
    }

    silu_kernel<<<(HID + 255) / 256, 256>>>(temb);
    ada_split_kernel<<<dim3(3 * HID / 256, ADA_SPLITS), 256>>>(ada_w);
    ada_reduce_kernel<<<(3 * HID + 255) / 256, 256>>>(ada_b);
    ln_kernel<<<L_, 256>>>(hidden);

    tgemm_k<2><<<dim3(N1 / 128, L_ / 128), 256, GEMM_SMEM>>>(
        p_normx, p_w1t, lin1_b, nullptr, nullptr, p_proj, p_cat, L_, N1, HID);

    qkv_kernel<<<dim3(L_, HEADS), HD>>>(cosb, sinb,
                                        (const float*)d_in[10], (const float*)d_in[11]);
    attn_kernel<<<dim3(L_ / 128, HEADS), 256, ATTN_SMEM>>>();

    tgemm_k<1><<<dim3(HID / 128, L_ / 128), 256, GEMM_SMEM>>>(
        p_cat, p_w2t, lin2_b, hidden, p_emb + 2 * HID, out, nullptr, L_, HID, K2);
}